// round 6
// baseline (speedup 1.0000x reference)
#include <cuda_runtime.h>
#include <cuda_bf16.h>
#include <cstdint>
#include <math.h>

typedef unsigned long long ull;
typedef unsigned int u32;

// ======================= problem constants =======================
#define BATCH   2
#define SEQ     2048
#define EMB     2048
#define NHEAD   32
#define HDIM    64
#define BT      (BATCH*SEQ)      // 4096
#define N_QKV   (3*EMB)          // 6144
#define KP      6144             // split-K' = 3*2048

// ======================= scratch (device globals) ================
__device__ float g_qkv[(size_t)BT * N_QKV];
__device__ float g_q  [(size_t)BATCH*NHEAD*SEQ*HDIM];
__device__ float g_k  [(size_t)BATCH*NHEAD*SEQ*HDIM];
__device__ float g_v  [(size_t)BATCH*NHEAD*SEQ*HDIM];
__device__ float g_ao [(size_t)BT * EMB];
__device__ __nv_bfloat16 g_Ax  [(size_t)BT * KP];
__device__ __nv_bfloat16 g_Aao [(size_t)BT * KP];
__device__ __nv_bfloat16 g_Bqkv[(size_t)N_QKV * KP];
__device__ __nv_bfloat16 g_Bout[(size_t)EMB * KP];

// ======================= helpers =================================
__device__ __forceinline__ ull pack2(float lo, float hi){
    ull r; asm("mov.b64 %0, {%1,%2};" : "=l"(r) : "f"(lo), "f"(hi)); return r;
}
__device__ __forceinline__ float2 unpack2(ull v){
    float2 f; asm("mov.b64 {%0,%1}, %2;" : "=f"(f.x), "=f"(f.y) : "l"(v)); return f;
}
__device__ __forceinline__ void fma2(ull &c, ull a, ull b){
    asm("fma.rn.f32x2 %0, %1, %2, %0;" : "+l"(c) : "l"(a), "l"(b));
}
__device__ __forceinline__ void mul2(ull &c, ull b){
    asm("mul.rn.f32x2 %0, %0, %1;" : "+l"(c) : "l"(b));
}
__device__ __forceinline__ u32 smem_u32(const void* p){
    u32 a; asm("{ .reg .u64 t; cvta.to.shared.u64 t, %1; cvt.u32.u64 %0, t; }" : "=r"(a) : "l"(p));
    return a;
}
#define SWZ128(off) ((off) ^ (((off) >> 3) & 0x70))

__device__ __forceinline__ void cpasync16(u32 daddr, const void* gptr){
    asm volatile("cp.async.cg.shared.global [%0], [%1], 16;" :: "r"(daddr), "l"(gptr));
}
#define CP_COMMIT() asm volatile("cp.async.commit_group;")
#define CP_WAIT(n)  asm volatile("cp.async.wait_group %0;" :: "n"(n))

__device__ __forceinline__ void ldsm4(u32* r, u32 addr){
    asm volatile("ldmatrix.sync.aligned.m8n8.x4.shared.b16 {%0,%1,%2,%3}, [%4];"
        : "=r"(r[0]), "=r"(r[1]), "=r"(r[2]), "=r"(r[3]) : "r"(addr));
}
__device__ __forceinline__ void mma16816(float* c, const u32* a, u32 b0, u32 b1){
    asm volatile("mma.sync.aligned.m16n8k16.row.col.f32.bf16.bf16.f32 "
        "{%0,%1,%2,%3}, {%4,%5,%6,%7}, {%8,%9}, {%0,%1,%2,%3};"
        : "+f"(c[0]), "+f"(c[1]), "+f"(c[2]), "+f"(c[3])
        : "r"(a[0]), "r"(a[1]), "r"(a[2]), "r"(a[3]), "r"(b0), "r"(b1));
}

// =============================================================================
// Split conversions: fp32 -> bf16 (hi, hi, lo) rows [R, 2048] -> [R, 6144]
// =============================================================================
__global__ void split_rows(const float* __restrict__ X, __nv_bfloat16* __restrict__ Ap, int R)
{
    size_t idx = (size_t)blockIdx.x*blockDim.x + threadIdx.x;
    if (idx >= (size_t)R*512) return;
    int m  = (int)(idx >> 9);
    int c4 = (int)(idx & 511) * 4;
    float4 x = *(const float4*)(X + (size_t)m*2048 + c4);
    float xs[4] = {x.x, x.y, x.z, x.w};
    __nv_bfloat16 hi[4], lo[4];
    #pragma unroll
    for (int j=0;j<4;j++){
        hi[j] = __float2bfloat16(xs[j]);
        lo[j] = __float2bfloat16(xs[j] - __bfloat162float(hi[j]));
    }
    __nv_bfloat16* row = Ap + (size_t)m*KP;
    *(ull*)(row + c4)        = *(const ull*)hi;
    *(ull*)(row + 2048 + c4) = *(const ull*)hi;
    *(ull*)(row + 4096 + c4) = *(const ull*)lo;
}

// W [2048, N] fp32 -> Bp [N, 6144] bf16 (hi at k, lo at 2048+k, hi at 4096+k)
__global__ void split_BT(const float* __restrict__ W, __nv_bfloat16* __restrict__ Bp, int N)
{
    __shared__ float tile[32][33];
    const int n0 = blockIdx.x*32, k0 = blockIdx.y*32;
    const int tx = threadIdx.x, ty = threadIdx.y;
    #pragma unroll
    for (int j=0;j<4;j++)
        tile[ty*4+j][tx] = W[(size_t)(k0+ty*4+j)*N + n0 + tx];
    __syncthreads();
    #pragma unroll
    for (int j=0;j<4;j++){
        const float v = tile[tx][ty*4+j];
        const __nv_bfloat16 hi = __float2bfloat16(v);
        const __nv_bfloat16 lo = __float2bfloat16(v - __bfloat162float(hi));
        __nv_bfloat16* row = Bp + (size_t)(n0+ty*4+j)*KP + k0 + tx;
        row[0]    = hi;
        row[2048] = lo;
        row[4096] = hi;
    }
}

// =============================================================================
// HMMA GEMM v4: C[M,N] = A'[M,KP] * B'[N,KP]^T + bias
// 128x256 CTA, 8 warps in 2x4 grid (64x64 each), 3-stage cp.async ring,
// GK=64, SW128 swizzle, one __syncthreads per chunk. 1 CTA/SM.
// =============================================================================
#define GK 64
#define NC (KP/GK)              // 96
#define STAGE_A 16384           // 128 rows x 128B
#define STAGE_B 32768           // 256 rows x 128B
#define STAGE   (STAGE_A + STAGE_B)    // 48 KB
#define NSTG 3
#define GEMM_SMEM (NSTG*STAGE)         // 144 KB

__global__ __launch_bounds__(256, 1)
void gemm_hmma(const __nv_bfloat16* __restrict__ A,
               const __nv_bfloat16* __restrict__ B,
               const float* __restrict__ bias,
               float* __restrict__ C, int N)
{
    extern __shared__ char smem[];
    const u32 sb = smem_u32(smem);
    const int tid  = threadIdx.x;
    const int wid  = tid >> 5;
    const int lane = tid & 31;
    const int wm = wid & 1;          // warp rows: wm*64..+63
    const int wn = wid >> 1;         // warp cols: wn*64..+63
    const int m0 = blockIdx.y * 128;
    const int n0 = blockIdx.x * 256;

    const __nv_bfloat16* Ab = A + (size_t)m0 * KP;
    const __nv_bfloat16* Bb = B + (size_t)n0 * KP;

    // per-stage loads (256 threads): A 128 rows x 8 granules (4/thread),
    // B 256 rows x 8 granules (8/thread)
    const int alr = tid >> 1;              // 0..127
    const int alk = (tid & 1) * 4;         // granule 0 or 4
    const int blr = tid;                   // 0..255
    auto load_stage = [&](int kc, u32 off){
        const __nv_bfloat16* Ag = Ab + (size_t)alr*KP + kc*GK + alk*8;
        #pragma unroll
        for (int j=0;j<4;j++)
            cpasync16(sb + off + SWZ128(alr*128 + (alk+j)*16), Ag + j*8);
        const __nv_bfloat16* Bg = Bb + (size_t)blr*KP + kc*GK;
        #pragma unroll
        for (int j=0;j<8;j++)
            cpasync16(sb + off + STAGE_A + SWZ128(blr*128 + j*16), Bg + j*8);
    };

    float acc[4][8][4];
    #pragma unroll
    for (int a=0;a<4;a++)
        #pragma unroll
        for (int b=0;b<8;b++)
            #pragma unroll
            for (int c=0;c<4;c++) acc[a][b][c] = 0.f;

    load_stage(0, 0);       CP_COMMIT();
    load_stage(1, STAGE);   CP_COMMIT();

    // ldmatrix lane offsets
    const int arow = wm*64 + (lane & 15);
    const int akof = (lane >> 4) * 8;
    const int brow = wn*64 + ((lane >> 4) & 1)*8 + (lane & 7);
    const int bkof = ((lane >> 3) & 1) * 8;

    int slot = 0;
    for (int i=0; i<NC; i++){
        CP_WAIT(1);
        __syncthreads();

        if (i+2 < NC){
            int ns = slot + 2; if (ns >= NSTG) ns -= NSTG;
            load_stage(i+2, (u32)ns * STAGE);
        }
        CP_COMMIT();

        const u32 abase = sb + (u32)slot * STAGE;
        const u32 bbase = abase + STAGE_A;

        #pragma unroll
        for (int ks=0; ks<4; ks++){
            const int k0 = ks*16;
            u32 afr[4][4];
            #pragma unroll
            for (int mf=0; mf<4; mf++)
                ldsm4(afr[mf], abase + SWZ128((arow + mf*16)*128 + (k0 + akof)*2));
            u32 bfr[4][4];
            #pragma unroll
            for (int nq=0; nq<4; nq++)
                ldsm4(bfr[nq], bbase + SWZ128((brow + nq*16)*128 + (k0 + bkof)*2));
            #pragma unroll
            for (int mf=0; mf<4; mf++)
                #pragma unroll
                for (int nq=0; nq<4; nq++){
                    mma16816(acc[mf][nq*2+0], afr[mf], bfr[nq][0], bfr[nq][1]);
                    mma16816(acc[mf][nq*2+1], afr[mf], bfr[nq][2], bfr[nq][3]);
                }
        }
        slot++; if (slot >= NSTG) slot = 0;
    }

    // epilogue
    #pragma unroll
    for (int mf=0; mf<4; mf++){
        const int r = m0 + wm*64 + mf*16 + (lane >> 2);
        #pragma unroll
        for (int nf=0; nf<8; nf++){
            const int c = n0 + wn*64 + nf*8 + (lane & 3)*2;
            const float b0 = bias[c], b1 = bias[c+1];
            float* cp = C + (size_t)r*N + c;
            *(float2*)cp = make_float2(acc[mf][nf][0] + b0, acc[mf][nf][1] + b1);
            *(float2*)(cp + 8*(size_t)N) = make_float2(acc[mf][nf][2] + b0, acc[mf][nf][3] + b1);
        }
    }
}

// =============================================================================
// RoPE + scatter
// =============================================================================
__global__ void rope_scatter(const float* __restrict__ qkv,
                             float* __restrict__ q, float* __restrict__ k,
                             float* __restrict__ v)
{
    const int bt = blockIdx.x;
    const int b = bt >> 11, t = bt & 2047;
    const float* row = qkv + (size_t)bt * N_QKV;

    for (int e = threadIdx.x; e < EMB; e += blockDim.x){
        const int h = e >> 6, d = e & 63;
        const size_t dst = ((size_t)(b*NHEAD + h) * SEQ + t) * HDIM + d;
        float qv = row[e];
        float kv = row[EMB + e];
        const float vv = row[2*EMB + e];
        if (d < 32){
            const int i = d & 15;
            const float invf = expf(-(float)i * (9.210340371976184f / 16.0f));
            const float ang = (float)t * invf;
            float sn, cs; sincosf(ang, &sn, &cs);
            if (d < 16){
                const float qx2 = row[e + 16];
                const float kx2 = row[EMB + e + 16];
                qv = qv*cs - qx2*sn;
                kv = kv*cs - kx2*sn;
            } else {
                const float qx1 = row[e - 16];
                const float kx1 = row[EMB + e - 16];
                qv = qx1*sn + qv*cs;
                kv = kx1*sn + kv*cs;
            }
        }
        q[dst] = qv * 0.125f;
        k[dst] = kv;
        v[dst] = vv;
    }
}

// =============================================================================
// Flash attention fp32, causal (f32x2 FMA path)
// =============================================================================
#define PAD 68
__global__ __launch_bounds__(256)
void flash_attn(const float* __restrict__ Q, const float* __restrict__ K,
                const float* __restrict__ V, float* __restrict__ Oo)
{
    extern __shared__ float sm[];
    float* Qs = sm;
    float* Ks = sm + 64*PAD;
    float* Vs = sm + 2*64*PAD;
    float* Ps = sm + 3*64*PAD;

    const int tid = threadIdx.x;
    const int tr = tid >> 4, tc = tid & 15;
    const int qt = blockIdx.x;
    const int bh = blockIdx.y;
    const size_t base = (size_t)bh * SEQ * HDIM;

    #pragma unroll
    for (int l=0;l<16;l++){
        int idx = tid + l*256;
        int r = idx >> 6, d = idx & 63;
        Qs[d*PAD + r] = Q[base + (size_t)(qt*64 + r)*HDIM + d];
    }

    float m[4], lsum[4];
    #pragma unroll
    for (int i=0;i<4;i++){ m[i] = -1e30f; lsum[i] = 0.f; }
    ull o2[4][2];
    #pragma unroll
    for (int i=0;i<4;i++){ o2[i][0]=0ULL; o2[i][1]=0ULL; }

    for (int kt = 0; kt <= qt; kt++){
        __syncthreads();
        #pragma unroll
        for (int l=0;l<16;l++){
            int idx = tid + l*256;
            int c = idx >> 6, d = idx & 63;
            Ks[d*PAD + c] = K[base + (size_t)(kt*64 + c)*HDIM + d];
            Vs[c*PAD + d] = V[base + (size_t)(kt*64 + c)*HDIM + d];
        }
        __syncthreads();

        ull s2[4][2];
        #pragma unroll
        for (int i=0;i<4;i++){ s2[i][0]=0ULL; s2[i][1]=0ULL; }
        #pragma unroll 8
        for (int d=0; d<64; d++){
            const float4 qv = *(const float4*)&Qs[d*PAD + tr*4];
            const ull* kp = (const ull*)&Ks[d*PAD + tc*4];
            const ull kb0 = kp[0], kb1 = kp[1];
            const float qa[4] = {qv.x, qv.y, qv.z, qv.w};
            #pragma unroll
            for (int i=0;i<4;i++){
                ull pa = pack2(qa[i], qa[i]);
                fma2(s2[i][0], pa, kb0);
                fma2(s2[i][1], pa, kb1);
            }
        }

        #pragma unroll
        for (int i=0;i<4;i++){
            float2 x0 = unpack2(s2[i][0]);
            float2 x1 = unpack2(s2[i][1]);
            float s0=x0.x, s1=x0.y, s2f=x1.x, s3=x1.y;
            if (kt == qt){
                const int rg = tr*4 + i;
                if (tc*4+0 > rg) s0  = -1e30f;
                if (tc*4+1 > rg) s1  = -1e30f;
                if (tc*4+2 > rg) s2f = -1e30f;
                if (tc*4+3 > rg) s3  = -1e30f;
            }
            float rm = fmaxf(fmaxf(s0,s1), fmaxf(s2f,s3));
            #pragma unroll
            for (int off=8; off; off>>=1)
                rm = fmaxf(rm, __shfl_xor_sync(0xffffffffu, rm, off));
            const float mn = fmaxf(m[i], rm);
            const float p0 = __expf(s0 - mn);
            const float p1 = __expf(s1 - mn);
            const float p2 = __expf(s2f - mn);
            const float p3 = __expf(s3 - mn);
            float rs = p0+p1+p2+p3;
            #pragma unroll
            for (int off=8; off; off>>=1)
                rs += __shfl_xor_sync(0xffffffffu, rs, off);
            const float corr = __expf(m[i] - mn);
            lsum[i] = lsum[i]*corr + rs;
            m[i] = mn;
            const ull pc = pack2(corr, corr);
            mul2(o2[i][0], pc);
            mul2(o2[i][1], pc);
            const int rr = tr*4 + i;
            Ps[(tc*4+0)*PAD + rr] = p0;
            Ps[(tc*4+1)*PAD + rr] = p1;
            Ps[(tc*4+2)*PAD + rr] = p2;
            Ps[(tc*4+3)*PAD + rr] = p3;
        }
        __syncthreads();

        #pragma unroll 8
        for (int c=0; c<64; c++){
            const float4 pv = *(const float4*)&Ps[c*PAD + tr*4];
            const ull* vp = (const ull*)&Vs[c*PAD + tc*4];
            const ull vb0 = vp[0], vb1 = vp[1];
            const float pa4[4] = {pv.x, pv.y, pv.z, pv.w};
            #pragma unroll
            for (int i=0;i<4;i++){
                ull pa = pack2(pa4[i], pa4[i]);
                fma2(o2[i][0], pa, vb0);
                fma2(o2[i][1], pa, vb1);
            }
        }
    }

    const int b = bh >> 5, h = bh & 31;
    #pragma unroll
    for (int i=0;i<4;i++){
        const float inv = 1.0f / lsum[i];
        float2 x0 = unpack2(o2[i][0]);
        float2 x1 = unpack2(o2[i][1]);
        const int t = qt*64 + tr*4 + i;
        float* op = Oo + ((size_t)(b*SEQ + t))*EMB + h*HDIM + tc*4;
        *(float4*)op = make_float4(x0.x*inv, x0.y*inv, x1.x*inv, x1.y*inv);
    }
}

// =============================================================================
extern "C" void kernel_launch(void* const* d_in, const int* in_sizes, int n_in,
                              void* d_out, int out_size)
{
    (void)in_sizes; (void)n_in; (void)out_size;
    const float* x    = (const float*)d_in[0];
    const float* Wqkv = (const float*)d_in[1];
    const float* bqkv = (const float*)d_in[2];
    const float* Wout = (const float*)d_in[3];
    const float* bout = (const float*)d_in[4];
    float* out = (float*)d_out;

    float *qkv, *q, *k, *v, *ao;
    __nv_bfloat16 *Ax, *Aao, *Bqkv, *Bout;
    cudaGetSymbolAddress((void**)&qkv, g_qkv);
    cudaGetSymbolAddress((void**)&q,   g_q);
    cudaGetSymbolAddress((void**)&k,   g_k);
    cudaGetSymbolAddress((void**)&v,   g_v);
    cudaGetSymbolAddress((void**)&ao,  g_ao);
    cudaGetSymbolAddress((void**)&Ax,   g_Ax);
    cudaGetSymbolAddress((void**)&Aao,  g_Aao);
    cudaGetSymbolAddress((void**)&Bqkv, g_Bqkv);
    cudaGetSymbolAddress((void**)&Bout, g_Bout);

    cudaFuncSetAttribute(gemm_hmma, cudaFuncAttributeMaxDynamicSharedMemorySize, GEMM_SMEM);

    // 0) split conversions
    split_rows<<<(BT*512 + 255)/256, 256>>>(x, Ax, BT);
    split_BT<<<dim3(N_QKV/32, EMB/32), dim3(32,8)>>>(Wqkv, Bqkv, N_QKV);
    split_BT<<<dim3(EMB/32,  EMB/32), dim3(32,8)>>>(Wout, Bout, EMB);

    // 1) QKV projection (tensor cores, mma.sync)
    gemm_hmma<<<dim3(N_QKV/256, BT/128), 256, GEMM_SMEM>>>(Ax, Bqkv, bqkv, qkv, N_QKV);

    // 2) RoPE + scatter
    rope_scatter<<<BT, 256>>>(qkv, q, k, v);

    // 3) causal flash attention (fp32)
    const int smem = 4 * 64 * PAD * (int)sizeof(float);
    cudaFuncSetAttribute(flash_attn, cudaFuncAttributeMaxDynamicSharedMemorySize, smem);
    flash_attn<<<dim3(SEQ/64, BATCH*NHEAD), 256, smem>>>(q, k, v, ao);

    // 4) output projection (tensor cores, mma.sync)
    split_rows<<<(BT*512 + 255)/256, 256>>>(ao, Aao, BT);
    gemm_hmma<<<dim3(EMB/256, BT/128), 256, GEMM_SMEM>>>(Aao, Bout, bout, out, EMB);
}

// round 7
// speedup vs baseline: 1.1978x; 1.1978x over previous
#include <cuda_runtime.h>
#include <cuda_bf16.h>
#include <cstdint>
#include <math.h>

typedef unsigned long long ull;
typedef unsigned int u32;

// ======================= problem constants =======================
#define BATCH   2
#define SEQ     2048
#define EMB     2048
#define NHEAD   32
#define HDIM    64
#define BT      (BATCH*SEQ)      // 4096
#define N_QKV   (3*EMB)          // 6144
#define KP      6144             // split-K' = 3*2048

// ======================= scratch (device globals) ================
__device__ float g_qkv[(size_t)BT * N_QKV];
__device__ float g_q  [(size_t)BATCH*NHEAD*SEQ*HDIM];
__device__ float g_k  [(size_t)BATCH*NHEAD*SEQ*HDIM];
__device__ float g_v  [(size_t)BATCH*NHEAD*SEQ*HDIM];
__device__ float g_ao [(size_t)BT * EMB];
__device__ __nv_bfloat16 g_Ax  [(size_t)BT * KP];
__device__ __nv_bfloat16 g_Aao [(size_t)BT * KP];
__device__ __nv_bfloat16 g_Bqkv[(size_t)N_QKV * KP];
__device__ __nv_bfloat16 g_Bout[(size_t)EMB * KP];

// ======================= helpers =================================
__device__ __forceinline__ ull pack2(float lo, float hi){
    ull r; asm("mov.b64 %0, {%1,%2};" : "=l"(r) : "f"(lo), "f"(hi)); return r;
}
__device__ __forceinline__ float2 unpack2(ull v){
    float2 f; asm("mov.b64 {%0,%1}, %2;" : "=f"(f.x), "=f"(f.y) : "l"(v)); return f;
}
__device__ __forceinline__ void fma2(ull &c, ull a, ull b){
    asm("fma.rn.f32x2 %0, %1, %2, %0;" : "+l"(c) : "l"(a), "l"(b));
}
__device__ __forceinline__ void mul2(ull &c, ull b){
    asm("mul.rn.f32x2 %0, %0, %1;" : "+l"(c) : "l"(b));
}
__device__ __forceinline__ u32 smem_u32(const void* p){
    u32 a; asm("{ .reg .u64 t; cvta.to.shared.u64 t, %1; cvt.u32.u64 %0, t; }" : "=r"(a) : "l"(p));
    return a;
}
#define SWZ128(off) ((off) ^ (((off) >> 3) & 0x70))

__device__ __forceinline__ void cpasync16(u32 daddr, const void* gptr){
    asm volatile("cp.async.cg.shared.global [%0], [%1], 16;" :: "r"(daddr), "l"(gptr));
}
#define CP_COMMIT() asm volatile("cp.async.commit_group;")
#define CP_WAIT(n)  asm volatile("cp.async.wait_group %0;" :: "n"(n))

__device__ __forceinline__ void ldsm4(u32* r, u32 addr){
    asm volatile("ldmatrix.sync.aligned.m8n8.x4.shared.b16 {%0,%1,%2,%3}, [%4];"
        : "=r"(r[0]), "=r"(r[1]), "=r"(r[2]), "=r"(r[3]) : "r"(addr));
}
__device__ __forceinline__ void mma16816(float* c, const u32* a, u32 b0, u32 b1){
    asm volatile("mma.sync.aligned.m16n8k16.row.col.f32.bf16.bf16.f32 "
        "{%0,%1,%2,%3}, {%4,%5,%6,%7}, {%8,%9}, {%0,%1,%2,%3};"
        : "+f"(c[0]), "+f"(c[1]), "+f"(c[2]), "+f"(c[3])
        : "r"(a[0]), "r"(a[1]), "r"(a[2]), "r"(a[3]), "r"(b0), "r"(b1));
}

// =============================================================================
// Split conversions: fp32 -> bf16 (hi, hi, lo) rows [R, 2048] -> [R, 6144]
// =============================================================================
__global__ void split_rows(const float* __restrict__ X, __nv_bfloat16* __restrict__ Ap, int R)
{
    size_t idx = (size_t)blockIdx.x*blockDim.x + threadIdx.x;
    if (idx >= (size_t)R*512) return;
    int m  = (int)(idx >> 9);
    int c4 = (int)(idx & 511) * 4;
    float4 x = *(const float4*)(X + (size_t)m*2048 + c4);
    float xs[4] = {x.x, x.y, x.z, x.w};
    __nv_bfloat16 hi[4], lo[4];
    #pragma unroll
    for (int j=0;j<4;j++){
        hi[j] = __float2bfloat16(xs[j]);
        lo[j] = __float2bfloat16(xs[j] - __bfloat162float(hi[j]));
    }
    __nv_bfloat16* row = Ap + (size_t)m*KP;
    *(ull*)(row + c4)        = *(const ull*)hi;
    *(ull*)(row + 2048 + c4) = *(const ull*)hi;
    *(ull*)(row + 4096 + c4) = *(const ull*)lo;
}

// W [2048, N] fp32 -> Bp [N, 6144] bf16 (hi at k, lo at 2048+k, hi at 4096+k)
__global__ void split_BT(const float* __restrict__ W, __nv_bfloat16* __restrict__ Bp, int N)
{
    __shared__ float tile[32][33];
    const int n0 = blockIdx.x*32, k0 = blockIdx.y*32;
    const int tx = threadIdx.x, ty = threadIdx.y;
    #pragma unroll
    for (int j=0;j<4;j++)
        tile[ty*4+j][tx] = W[(size_t)(k0+ty*4+j)*N + n0 + tx];
    __syncthreads();
    #pragma unroll
    for (int j=0;j<4;j++){
        const float v = tile[tx][ty*4+j];
        const __nv_bfloat16 hi = __float2bfloat16(v);
        const __nv_bfloat16 lo = __float2bfloat16(v - __bfloat162float(hi));
        __nv_bfloat16* row = Bp + (size_t)(n0+ty*4+j)*KP + k0 + tx;
        row[0]    = hi;
        row[2048] = lo;
        row[4096] = hi;
    }
}

// =============================================================================
// HMMA GEMM v5: C[M,N] = A'[M,KP] * B'[N,KP]^T + bias
// 128x256 CTA, 16 warps in 4x4 grid, each warp 32x64 (round-5 shape),
// 3-stage cp.async ring, GK=64, SW128 swizzle, one barrier/chunk. 1 CTA/SM.
// =============================================================================
#define GK 64
#define NC (KP/GK)              // 96
#define STAGE_A 16384           // 128 rows x 128B
#define STAGE_B 32768           // 256 rows x 128B
#define STAGE   (STAGE_A + STAGE_B)    // 48 KB
#define NSTG 3
#define GEMM_SMEM (NSTG*STAGE)         // 144 KB

__global__ __launch_bounds__(512, 1)
void gemm_hmma(const __nv_bfloat16* __restrict__ A,
               const __nv_bfloat16* __restrict__ B,
               const float* __restrict__ bias,
               float* __restrict__ C, int N)
{
    extern __shared__ char smem[];
    const u32 sb = smem_u32(smem);
    const int tid  = threadIdx.x;
    const int wid  = tid >> 5;
    const int lane = tid & 31;
    const int wm = wid & 3;          // warp rows: wm*32..+31
    const int wn = wid >> 2;         // warp cols: wn*64..+63
    const int m0 = blockIdx.y * 128;
    const int n0 = blockIdx.x * 256;

    const __nv_bfloat16* Ab = A + (size_t)m0 * KP;
    const __nv_bfloat16* Bb = B + (size_t)n0 * KP;

    // per-stage loads (512 threads):
    // A: 128 rows x 8 granules (16B) = 1024 -> 2/thread
    // B: 256 rows x 8 granules       = 2048 -> 4/thread
    const int alr = tid >> 2;              // 0..127
    const int alk = (tid & 3) * 2;         // granules {0,2,4,6}
    const int blr = tid >> 1;              // 0..255
    const int blk = (tid & 1) * 4;         // granules {0,4}
    auto load_stage = [&](int kc, u32 off){
        const __nv_bfloat16* Ag = Ab + (size_t)alr*KP + kc*GK + alk*8;
        #pragma unroll
        for (int j=0;j<2;j++)
            cpasync16(sb + off + SWZ128(alr*128 + (alk+j)*16), Ag + j*8);
        const __nv_bfloat16* Bg = Bb + (size_t)blr*KP + kc*GK + blk*8;
        #pragma unroll
        for (int j=0;j<4;j++)
            cpasync16(sb + off + STAGE_A + SWZ128(blr*128 + (blk+j)*16), Bg + j*8);
    };

    float acc[2][8][4];
    #pragma unroll
    for (int a=0;a<2;a++)
        #pragma unroll
        for (int b=0;b<8;b++)
            #pragma unroll
            for (int c=0;c<4;c++) acc[a][b][c] = 0.f;

    load_stage(0, 0);       CP_COMMIT();
    load_stage(1, STAGE);   CP_COMMIT();

    // ldmatrix lane offsets (round-5 32x64 warp tile)
    const int arow = wm*32 + (lane & 15);
    const int akof = (lane >> 4) * 8;
    const int brow = wn*64 + ((lane >> 4) & 1)*8 + (lane & 7);
    const int bkof = ((lane >> 3) & 1) * 8;

    int slot = 0;
    for (int i=0; i<NC; i++){
        CP_WAIT(1);
        __syncthreads();

        if (i+2 < NC){
            int ns = slot + 2; if (ns >= NSTG) ns -= NSTG;
            load_stage(i+2, (u32)ns * STAGE);
        }
        CP_COMMIT();

        const u32 abase = sb + (u32)slot * STAGE;
        const u32 bbase = abase + STAGE_A;

        #pragma unroll
        for (int ks=0; ks<4; ks++){
            const int k0 = ks*16;
            u32 afr[2][4];
            #pragma unroll
            for (int mf=0; mf<2; mf++)
                ldsm4(afr[mf], abase + SWZ128((arow + mf*16)*128 + (k0 + akof)*2));
            u32 bfr[4][4];
            #pragma unroll
            for (int nq=0; nq<4; nq++)
                ldsm4(bfr[nq], bbase + SWZ128((brow + nq*16)*128 + (k0 + bkof)*2));
            #pragma unroll
            for (int mf=0; mf<2; mf++)
                #pragma unroll
                for (int nq=0; nq<4; nq++){
                    mma16816(acc[mf][nq*2+0], afr[mf], bfr[nq][0], bfr[nq][1]);
                    mma16816(acc[mf][nq*2+1], afr[mf], bfr[nq][2], bfr[nq][3]);
                }
        }
        slot++; if (slot >= NSTG) slot = 0;
    }

    // epilogue
    #pragma unroll
    for (int mf=0; mf<2; mf++){
        const int r = m0 + wm*32 + mf*16 + (lane >> 2);
        #pragma unroll
        for (int nf=0; nf<8; nf++){
            const int c = n0 + wn*64 + nf*8 + (lane & 3)*2;
            const float b0 = bias[c], b1 = bias[c+1];
            float* cp = C + (size_t)r*N + c;
            *(float2*)cp = make_float2(acc[mf][nf][0] + b0, acc[mf][nf][1] + b1);
            *(float2*)(cp + 8*(size_t)N) = make_float2(acc[mf][nf][2] + b0, acc[mf][nf][3] + b1);
        }
    }
}

// =============================================================================
// RoPE + scatter
// =============================================================================
__global__ void rope_scatter(const float* __restrict__ qkv,
                             float* __restrict__ q, float* __restrict__ k,
                             float* __restrict__ v)
{
    const int bt = blockIdx.x;
    const int b = bt >> 11, t = bt & 2047;
    const float* row = qkv + (size_t)bt * N_QKV;

    for (int e = threadIdx.x; e < EMB; e += blockDim.x){
        const int h = e >> 6, d = e & 63;
        const size_t dst = ((size_t)(b*NHEAD + h) * SEQ + t) * HDIM + d;
        float qv = row[e];
        float kv = row[EMB + e];
        const float vv = row[2*EMB + e];
        if (d < 32){
            const int i = d & 15;
            const float invf = expf(-(float)i * (9.210340371976184f / 16.0f));
            const float ang = (float)t * invf;
            float sn, cs; sincosf(ang, &sn, &cs);
            if (d < 16){
                const float qx2 = row[e + 16];
                const float kx2 = row[EMB + e + 16];
                qv = qv*cs - qx2*sn;
                kv = kv*cs - kx2*sn;
            } else {
                const float qx1 = row[e - 16];
                const float kx1 = row[EMB + e - 16];
                qv = qx1*sn + qv*cs;
                kv = kx1*sn + kv*cs;
            }
        }
        q[dst] = qv * 0.125f;
        k[dst] = kv;
        v[dst] = vv;
    }
}

// =============================================================================
// Flash attention fp32, causal (f32x2 FMA path)
// =============================================================================
#define PAD 68
__global__ __launch_bounds__(256)
void flash_attn(const float* __restrict__ Q, const float* __restrict__ K,
                const float* __restrict__ V, float* __restrict__ Oo)
{
    extern __shared__ float sm[];
    float* Qs = sm;
    float* Ks = sm + 64*PAD;
    float* Vs = sm + 2*64*PAD;
    float* Ps = sm + 3*64*PAD;

    const int tid = threadIdx.x;
    const int tr = tid >> 4, tc = tid & 15;
    const int qt = blockIdx.x;
    const int bh = blockIdx.y;
    const size_t base = (size_t)bh * SEQ * HDIM;

    #pragma unroll
    for (int l=0;l<16;l++){
        int idx = tid + l*256;
        int r = idx >> 6, d = idx & 63;
        Qs[d*PAD + r] = Q[base + (size_t)(qt*64 + r)*HDIM + d];
    }

    float m[4], lsum[4];
    #pragma unroll
    for (int i=0;i<4;i++){ m[i] = -1e30f; lsum[i] = 0.f; }
    ull o2[4][2];
    #pragma unroll
    for (int i=0;i<4;i++){ o2[i][0]=0ULL; o2[i][1]=0ULL; }

    for (int kt = 0; kt <= qt; kt++){
        __syncthreads();
        #pragma unroll
        for (int l=0;l<16;l++){
            int idx = tid + l*256;
            int c = idx >> 6, d = idx & 63;
            Ks[d*PAD + c] = K[base + (size_t)(kt*64 + c)*HDIM + d];
            Vs[c*PAD + d] = V[base + (size_t)(kt*64 + c)*HDIM + d];
        }
        __syncthreads();

        ull s2[4][2];
        #pragma unroll
        for (int i=0;i<4;i++){ s2[i][0]=0ULL; s2[i][1]=0ULL; }
        #pragma unroll 8
        for (int d=0; d<64; d++){
            const float4 qv = *(const float4*)&Qs[d*PAD + tr*4];
            const ull* kp = (const ull*)&Ks[d*PAD + tc*4];
            const ull kb0 = kp[0], kb1 = kp[1];
            const float qa[4] = {qv.x, qv.y, qv.z, qv.w};
            #pragma unroll
            for (int i=0;i<4;i++){
                ull pa = pack2(qa[i], qa[i]);
                fma2(s2[i][0], pa, kb0);
                fma2(s2[i][1], pa, kb1);
            }
        }

        #pragma unroll
        for (int i=0;i<4;i++){
            float2 x0 = unpack2(s2[i][0]);
            float2 x1 = unpack2(s2[i][1]);
            float s0=x0.x, s1=x0.y, s2f=x1.x, s3=x1.y;
            if (kt == qt){
                const int rg = tr*4 + i;
                if (tc*4+0 > rg) s0  = -1e30f;
                if (tc*4+1 > rg) s1  = -1e30f;
                if (tc*4+2 > rg) s2f = -1e30f;
                if (tc*4+3 > rg) s3  = -1e30f;
            }
            float rm = fmaxf(fmaxf(s0,s1), fmaxf(s2f,s3));
            #pragma unroll
            for (int off=8; off; off>>=1)
                rm = fmaxf(rm, __shfl_xor_sync(0xffffffffu, rm, off));
            const float mn = fmaxf(m[i], rm);
            const float p0 = __expf(s0 - mn);
            const float p1 = __expf(s1 - mn);
            const float p2 = __expf(s2f - mn);
            const float p3 = __expf(s3 - mn);
            float rs = p0+p1+p2+p3;
            #pragma unroll
            for (int off=8; off; off>>=1)
                rs += __shfl_xor_sync(0xffffffffu, rs, off);
            const float corr = __expf(m[i] - mn);
            lsum[i] = lsum[i]*corr + rs;
            m[i] = mn;
            const ull pc = pack2(corr, corr);
            mul2(o2[i][0], pc);
            mul2(o2[i][1], pc);
            const int rr = tr*4 + i;
            Ps[(tc*4+0)*PAD + rr] = p0;
            Ps[(tc*4+1)*PAD + rr] = p1;
            Ps[(tc*4+2)*PAD + rr] = p2;
            Ps[(tc*4+3)*PAD + rr] = p3;
        }
        __syncthreads();

        #pragma unroll 8
        for (int c=0; c<64; c++){
            const float4 pv = *(const float4*)&Ps[c*PAD + tr*4];
            const ull* vp = (const ull*)&Vs[c*PAD + tc*4];
            const ull vb0 = vp[0], vb1 = vp[1];
            const float pa4[4] = {pv.x, pv.y, pv.z, pv.w};
            #pragma unroll
            for (int i=0;i<4;i++){
                ull pa = pack2(pa4[i], pa4[i]);
                fma2(o2[i][0], pa, vb0);
                fma2(o2[i][1], pa, vb1);
            }
        }
    }

    const int b = bh >> 5, h = bh & 31;
    #pragma unroll
    for (int i=0;i<4;i++){
        const float inv = 1.0f / lsum[i];
        float2 x0 = unpack2(o2[i][0]);
        float2 x1 = unpack2(o2[i][1]);
        const int t = qt*64 + tr*4 + i;
        float* op = Oo + ((size_t)(b*SEQ + t))*EMB + h*HDIM + tc*4;
        *(float4*)op = make_float4(x0.x*inv, x0.y*inv, x1.x*inv, x1.y*inv);
    }
}

// =============================================================================
extern "C" void kernel_launch(void* const* d_in, const int* in_sizes, int n_in,
                              void* d_out, int out_size)
{
    (void)in_sizes; (void)n_in; (void)out_size;
    const float* x    = (const float*)d_in[0];
    const float* Wqkv = (const float*)d_in[1];
    const float* bqkv = (const float*)d_in[2];
    const float* Wout = (const float*)d_in[3];
    const float* bout = (const float*)d_in[4];
    float* out = (float*)d_out;

    float *qkv, *q, *k, *v, *ao;
    __nv_bfloat16 *Ax, *Aao, *Bqkv, *Bout;
    cudaGetSymbolAddress((void**)&qkv, g_qkv);
    cudaGetSymbolAddress((void**)&q,   g_q);
    cudaGetSymbolAddress((void**)&k,   g_k);
    cudaGetSymbolAddress((void**)&v,   g_v);
    cudaGetSymbolAddress((void**)&ao,  g_ao);
    cudaGetSymbolAddress((void**)&Ax,   g_Ax);
    cudaGetSymbolAddress((void**)&Aao,  g_Aao);
    cudaGetSymbolAddress((void**)&Bqkv, g_Bqkv);
    cudaGetSymbolAddress((void**)&Bout, g_Bout);

    cudaFuncSetAttribute(gemm_hmma, cudaFuncAttributeMaxDynamicSharedMemorySize, GEMM_SMEM);

    // 0) split conversions
    split_rows<<<(BT*512 + 255)/256, 256>>>(x, Ax, BT);
    split_BT<<<dim3(N_QKV/32, EMB/32), dim3(32,8)>>>(Wqkv, Bqkv, N_QKV);
    split_BT<<<dim3(EMB/32,  EMB/32), dim3(32,8)>>>(Wout, Bout, EMB);

    // 1) QKV projection (tensor cores, mma.sync)
    gemm_hmma<<<dim3(N_QKV/256, BT/128), 512, GEMM_SMEM>>>(Ax, Bqkv, bqkv, qkv, N_QKV);

    // 2) RoPE + scatter
    rope_scatter<<<BT, 256>>>(qkv, q, k, v);

    // 3) causal flash attention (fp32)
    const int smem = 4 * 64 * PAD * (int)sizeof(float);
    cudaFuncSetAttribute(flash_attn, cudaFuncAttributeMaxDynamicSharedMemorySize, smem);
    flash_attn<<<dim3(SEQ/64, BATCH*NHEAD), 256, smem>>>(q, k, v, ao);

    // 4) output projection (tensor cores, mma.sync)
    split_rows<<<(BT*512 + 255)/256, 256>>>(ao, Aao, BT);
    gemm_hmma<<<dim3(EMB/256, BT/128), 512, GEMM_SMEM>>>(Aao, Bout, bout, out, EMB);
}

// round 9
// speedup vs baseline: 1.8803x; 1.5698x over previous
#include <cuda_runtime.h>
#include <cuda_bf16.h>
#include <cuda_fp16.h>
#include <cstdint>
#include <math.h>

typedef unsigned long long ull;
typedef unsigned int u32;

// ======================= problem constants =======================
#define BATCH   2
#define SEQ     2048
#define EMB     2048
#define NHEAD   32
#define HDIM    64
#define BT      (BATCH*SEQ)      // 4096
#define N_QKV   (3*EMB)          // 6144
#define KP      6144             // split-K' = 3*2048

// ======================= scratch (device globals) ================
__device__ float g_qkv[(size_t)BT * N_QKV];
__device__ float g_ao [(size_t)BT * EMB];
__device__ __half g_qh[(size_t)BATCH*NHEAD*SEQ*HDIM];  // [b,h,t,d] (scaled)
__device__ __half g_kh[(size_t)BATCH*NHEAD*SEQ*HDIM];  // [b,h,t,d]
__device__ __half g_vt[(size_t)BATCH*NHEAD*HDIM*SEQ];  // [b,h,d,t] transposed
__device__ __nv_bfloat16 g_Ax  [(size_t)BT * KP];
__device__ __nv_bfloat16 g_Aao [(size_t)BT * KP];
__device__ __nv_bfloat16 g_Bqkv[(size_t)N_QKV * KP];
__device__ __nv_bfloat16 g_Bout[(size_t)EMB * KP];

// ======================= helpers =================================
__device__ __forceinline__ u32 smem_u32(const void* p){
    u32 a; asm("{ .reg .u64 t; cvta.to.shared.u64 t, %1; cvt.u32.u64 %0, t; }" : "=r"(a) : "l"(p));
    return a;
}
#define SWZ128(off) ((off) ^ (((off) >> 3) & 0x70))

__device__ __forceinline__ void cpasync16(u32 daddr, const void* gptr){
    asm volatile("cp.async.cg.shared.global [%0], [%1], 16;" :: "r"(daddr), "l"(gptr));
}
#define CP_COMMIT() asm volatile("cp.async.commit_group;")
#define CP_WAIT(n)  asm volatile("cp.async.wait_group %0;" :: "n"(n))

__device__ __forceinline__ void ldsm4(u32* r, u32 addr){
    asm volatile("ldmatrix.sync.aligned.m8n8.x4.shared.b16 {%0,%1,%2,%3}, [%4];"
        : "=r"(r[0]), "=r"(r[1]), "=r"(r[2]), "=r"(r[3]) : "r"(addr));
}
__device__ __forceinline__ void mma16816(float* c, const u32* a, u32 b0, u32 b1){
    asm volatile("mma.sync.aligned.m16n8k16.row.col.f32.bf16.bf16.f32 "
        "{%0,%1,%2,%3}, {%4,%5,%6,%7}, {%8,%9}, {%0,%1,%2,%3};"
        : "+f"(c[0]), "+f"(c[1]), "+f"(c[2]), "+f"(c[3])
        : "r"(a[0]), "r"(a[1]), "r"(a[2]), "r"(a[3]), "r"(b0), "r"(b1));
}
__device__ __forceinline__ void mma16816h(float* c, const u32* a, u32 b0, u32 b1){
    asm volatile("mma.sync.aligned.m16n8k16.row.col.f32.f16.f16.f32 "
        "{%0,%1,%2,%3}, {%4,%5,%6,%7}, {%8,%9}, {%0,%1,%2,%3};"
        : "+f"(c[0]), "+f"(c[1]), "+f"(c[2]), "+f"(c[3])
        : "r"(a[0]), "r"(a[1]), "r"(a[2]), "r"(a[3]), "r"(b0), "r"(b1));
}
// pack two fp32 -> f16x2 register: lo half = a, hi half = b
__device__ __forceinline__ u32 h2pack(float a, float b){
    u32 r;
    asm("cvt.rn.f16x2.f32 %0, %2, %1;" : "=r"(r) : "f"(a), "f"(b));
    return r;
}

// =============================================================================
// Split conversions: fp32 -> bf16 (hi, hi, lo) rows [R, 2048] -> [R, 6144]
// =============================================================================
__global__ void split_rows(const float* __restrict__ X, __nv_bfloat16* __restrict__ Ap, int R)
{
    size_t idx = (size_t)blockIdx.x*blockDim.x + threadIdx.x;
    if (idx >= (size_t)R*512) return;
    int m  = (int)(idx >> 9);
    int c4 = (int)(idx & 511) * 4;
    float4 x = *(const float4*)(X + (size_t)m*2048 + c4);
    float xs[4] = {x.x, x.y, x.z, x.w};
    __nv_bfloat16 hi[4], lo[4];
    #pragma unroll
    for (int j=0;j<4;j++){
        hi[j] = __float2bfloat16(xs[j]);
        lo[j] = __float2bfloat16(xs[j] - __bfloat162float(hi[j]));
    }
    __nv_bfloat16* row = Ap + (size_t)m*KP;
    *(ull*)(row + c4)        = *(const ull*)hi;
    *(ull*)(row + 2048 + c4) = *(const ull*)hi;
    *(ull*)(row + 4096 + c4) = *(const ull*)lo;
}

__global__ void split_BT(const float* __restrict__ W, __nv_bfloat16* __restrict__ Bp, int N)
{
    __shared__ float tile[32][33];
    const int n0 = blockIdx.x*32, k0 = blockIdx.y*32;
    const int tx = threadIdx.x, ty = threadIdx.y;
    #pragma unroll
    for (int j=0;j<4;j++)
        tile[ty*4+j][tx] = W[(size_t)(k0+ty*4+j)*N + n0 + tx];
    __syncthreads();
    #pragma unroll
    for (int j=0;j<4;j++){
        const float v = tile[tx][ty*4+j];
        const __nv_bfloat16 hi = __float2bfloat16(v);
        const __nv_bfloat16 lo = __float2bfloat16(v - __bfloat162float(hi));
        __nv_bfloat16* row = Bp + (size_t)(n0+ty*4+j)*KP + k0 + tx;
        row[0]    = hi;
        row[2048] = lo;
        row[4096] = hi;
    }
}

// =============================================================================
// HMMA GEMM (round-7 config, at the mma.sync ceiling)
// =============================================================================
#define GK 64
#define NC (KP/GK)
#define STAGE_A 16384
#define STAGE_B 32768
#define STAGE   (STAGE_A + STAGE_B)
#define NSTG 3
#define GEMM_SMEM (NSTG*STAGE)

__global__ __launch_bounds__(512, 1)
void gemm_hmma(const __nv_bfloat16* __restrict__ A,
               const __nv_bfloat16* __restrict__ B,
               const float* __restrict__ bias,
               float* __restrict__ C, int N)
{
    extern __shared__ char smem[];
    const u32 sb = smem_u32(smem);
    const int tid  = threadIdx.x;
    const int wid  = tid >> 5;
    const int lane = tid & 31;
    const int wm = wid & 3;
    const int wn = wid >> 2;
    const int m0 = blockIdx.y * 128;
    const int n0 = blockIdx.x * 256;

    const __nv_bfloat16* Ab = A + (size_t)m0 * KP;
    const __nv_bfloat16* Bb = B + (size_t)n0 * KP;

    const int alr = tid >> 2;
    const int alk = (tid & 3) * 2;
    const int blr = tid >> 1;
    const int blk = (tid & 1) * 4;
    auto load_stage = [&](int kc, u32 off){
        const __nv_bfloat16* Ag = Ab + (size_t)alr*KP + kc*GK + alk*8;
        #pragma unroll
        for (int j=0;j<2;j++)
            cpasync16(sb + off + SWZ128(alr*128 + (alk+j)*16), Ag + j*8);
        const __nv_bfloat16* Bg = Bb + (size_t)blr*KP + kc*GK + blk*8;
        #pragma unroll
        for (int j=0;j<4;j++)
            cpasync16(sb + off + STAGE_A + SWZ128(blr*128 + (blk+j)*16), Bg + j*8);
    };

    float acc[2][8][4];
    #pragma unroll
    for (int a=0;a<2;a++)
        #pragma unroll
        for (int b=0;b<8;b++)
            #pragma unroll
            for (int c=0;c<4;c++) acc[a][b][c] = 0.f;

    load_stage(0, 0);       CP_COMMIT();
    load_stage(1, STAGE);   CP_COMMIT();

    const int arow = wm*32 + (lane & 15);
    const int akof = (lane >> 4) * 8;
    const int brow = wn*64 + ((lane >> 4) & 1)*8 + (lane & 7);
    const int bkof = ((lane >> 3) & 1) * 8;

    int slot = 0;
    for (int i=0; i<NC; i++){
        CP_WAIT(1);
        __syncthreads();

        if (i+2 < NC){
            int ns = slot + 2; if (ns >= NSTG) ns -= NSTG;
            load_stage(i+2, (u32)ns * STAGE);
        }
        CP_COMMIT();

        const u32 abase = sb + (u32)slot * STAGE;
        const u32 bbase = abase + STAGE_A;

        #pragma unroll
        for (int ks=0; ks<4; ks++){
            const int k0 = ks*16;
            u32 afr[2][4];
            #pragma unroll
            for (int mf=0; mf<2; mf++)
                ldsm4(afr[mf], abase + SWZ128((arow + mf*16)*128 + (k0 + akof)*2));
            u32 bfr[4][4];
            #pragma unroll
            for (int nq=0; nq<4; nq++)
                ldsm4(bfr[nq], bbase + SWZ128((brow + nq*16)*128 + (k0 + bkof)*2));
            #pragma unroll
            for (int mf=0; mf<2; mf++)
                #pragma unroll
                for (int nq=0; nq<4; nq++){
                    mma16816(acc[mf][nq*2+0], afr[mf], bfr[nq][0], bfr[nq][1]);
                    mma16816(acc[mf][nq*2+1], afr[mf], bfr[nq][2], bfr[nq][3]);
                }
        }
        slot++; if (slot >= NSTG) slot = 0;
    }

    #pragma unroll
    for (int mf=0; mf<2; mf++){
        const int r = m0 + wm*32 + mf*16 + (lane >> 2);
        #pragma unroll
        for (int nf=0; nf<8; nf++){
            const int c = n0 + wn*64 + nf*8 + (lane & 3)*2;
            const float b0 = bias[c], b1 = bias[c+1];
            float* cp = C + (size_t)r*N + c;
            *(float2*)cp = make_float2(acc[mf][nf][0] + b0, acc[mf][nf][1] + b1);
            *(float2*)(cp + 8*(size_t)N) = make_float2(acc[mf][nf][2] + b0, acc[mf][nf][3] + b1);
        }
    }
}

// =============================================================================
// RoPE + scatter to fp16: qh/kh [b,h,t,d], vt [b,h,d,t]
// =============================================================================
__global__ void rope_scatter(const float* __restrict__ qkv,
                             __half* __restrict__ qh, __half* __restrict__ kh,
                             __half* __restrict__ vt)
{
    const int bt = blockIdx.x;
    const int b = bt >> 11, t = bt & 2047;
    const float* row = qkv + (size_t)bt * N_QKV;

    for (int e = threadIdx.x; e < EMB; e += blockDim.x){
        const int h = e >> 6, d = e & 63;
        const size_t dst = ((size_t)(b*NHEAD + h) * SEQ + t) * HDIM + d;
        float qv = row[e];
        float kv = row[EMB + e];
        const float vv = row[2*EMB + e];
        if (d < 32){
            const int i = d & 15;
            const float invf = expf(-(float)i * (9.210340371976184f / 16.0f));
            const float ang = (float)t * invf;
            float sn, cs; sincosf(ang, &sn, &cs);
            if (d < 16){
                const float qx2 = row[e + 16];
                const float kx2 = row[EMB + e + 16];
                qv = qv*cs - qx2*sn;
                kv = kv*cs - kx2*sn;
            } else {
                const float qx1 = row[e - 16];
                const float kx1 = row[EMB + e - 16];
                qv = qx1*sn + qv*cs;
                kv = kx1*sn + kv*cs;
            }
        }
        qh[dst] = __float2half(qv * 0.125f);
        kh[dst] = __float2half(kv);
        vt[((size_t)(b*NHEAD + h) * HDIM + d) * SEQ + t] = __float2half(vv);
    }
}

// =============================================================================
// Flash attention, fp16 HMMA, causal.
// Block: 128 q rows x one (b,h). 8 warps; warp = 16 q rows x 64.
// K/V tiles of 64 keys, 3-stage cp.async ring. V pre-transposed [d][t].
// =============================================================================
#define FA_KV   16384                    // Ks 8KB + Vs 8KB per stage
#define FA_SMEM (16384 + 3*FA_KV)        // Qs + 3 stages = 64 KB

__global__ __launch_bounds__(256, 2)
void flash_hmma(const __half* __restrict__ Qh, const __half* __restrict__ Kh,
                const __half* __restrict__ Vt, float* __restrict__ Oo)
{
    extern __shared__ char smem[];
    const u32 sb = smem_u32(smem);
    const int tid = threadIdx.x, wid = tid >> 5, lane = tid & 31;
    const int qt = (int)gridDim.x - 1 - (int)blockIdx.x;   // heavy tiles first
    const int bh = blockIdx.y;
    const size_t base = (size_t)bh * SEQ * HDIM;
    const int nkt = 2*qt + 2;

    // ---- load Q tile [128][64] fp16, SW128 rows of 128B
    {
        const int r = tid >> 1;
        const int g = (tid & 1) * 4;
        const __half* Qg = Qh + base + (size_t)(qt*128 + r)*HDIM + g*8;
        #pragma unroll
        for (int j=0;j<4;j++)
            cpasync16(sb + SWZ128(r*128 + (g+j)*16), Qg + j*8);
    }
    // ---- K/V tile loader: Ks [t64][d64], Vs [d64][t64]
    const int kvr = tid >> 2;
    const int kvg = (tid & 3) * 2;
    auto load_kv = [&](int kt, u32 off){
        const __half* Kg = Kh + base + (size_t)(kt*64 + kvr)*HDIM + kvg*8;
        cpasync16(sb + off        + SWZ128(kvr*128 +  kvg   *16), Kg);
        cpasync16(sb + off        + SWZ128(kvr*128 + (kvg+1)*16), Kg + 8);
        const __half* Vg = Vt + base + (size_t)kvr*SEQ + kt*64 + kvg*8;
        cpasync16(sb + off + 8192 + SWZ128(kvr*128 +  kvg   *16), Vg);
        cpasync16(sb + off + 8192 + SWZ128(kvr*128 + (kvg+1)*16), Vg + 8);
    };

    load_kv(0, 16384);              CP_COMMIT();   // group: Q + kv0
    if (nkt > 1) load_kv(1, 16384 + FA_KV);
    CP_COMMIT();                                    // group: kv1

    CP_WAIT(1);
    __syncthreads();   // Q + kv0 ready

    // ---- Q fragments (held for the whole block)
    u32 aq[4][4];
    {
        const int arow = wid*16 + (lane & 15);
        const int akof = (lane >> 4) * 8;
        #pragma unroll
        for (int ks=0; ks<4; ks++)
            ldsm4(aq[ks], sb + SWZ128(arow*128 + (ks*16 + akof)*2));
    }

    const int brow = ((lane >> 4) & 1)*8 + (lane & 7);
    const int bkof = ((lane >> 3) & 1) * 8;
    const int rq   = qt*128 + wid*16 + (lane >> 2);   // global q row (c0/c1)

    float oacc[8][4];
    #pragma unroll
    for (int j=0;j<8;j++){ oacc[j][0]=0.f; oacc[j][1]=0.f; oacc[j][2]=0.f; oacc[j][3]=0.f; }
    float m0 = -1e30f, m1 = -1e30f, l0 = 0.f, l1 = 0.f;

    int slot = 0;
    for (int kt = 0; kt < nkt; kt++){
        if (kt > 0){ CP_WAIT(1); __syncthreads(); }
        if (kt+2 < nkt){
            int ns = slot + 2; if (ns >= 3) ns -= 3;
            load_kv(kt+2, 16384 + (u32)ns*FA_KV);
        }
        CP_COMMIT();

        const u32 kbase = sb + 16384 + (u32)slot*FA_KV;
        const u32 vbase = kbase + 8192;

        // ---- S = Q K^T
        float sacc[8][4];
        #pragma unroll
        for (int j=0;j<8;j++){ sacc[j][0]=0.f; sacc[j][1]=0.f; sacc[j][2]=0.f; sacc[j][3]=0.f; }
        #pragma unroll
        for (int ks=0; ks<4; ks++){
            #pragma unroll
            for (int nq=0; nq<4; nq++){
                u32 bfr[4];
                ldsm4(bfr, kbase + SWZ128((nq*16 + brow)*128 + (ks*16 + bkof)*2));
                mma16816h(sacc[nq*2+0], aq[ks], bfr[0], bfr[1]);
                mma16816h(sacc[nq*2+1], aq[ks], bfr[2], bfr[3]);
            }
        }

        // ---- causal mask (only tiles overlapping the diagonal)
        if (kt >= 2*qt){
            #pragma unroll
            for (int j=0;j<8;j++){
                const int c = kt*64 + (j>>1)*16 + ((j&1)<<3) + ((lane&3)<<1);
                if (c   > rq)   sacc[j][0] = -1e30f;
                if (c+1 > rq)   sacc[j][1] = -1e30f;
                if (c   > rq+8) sacc[j][2] = -1e30f;
                if (c+1 > rq+8) sacc[j][3] = -1e30f;
            }
        }

        // ---- online softmax (rows rq and rq+8)
        float mx0 = -1e30f, mx1 = -1e30f;
        #pragma unroll
        for (int j=0;j<8;j++){
            mx0 = fmaxf(mx0, fmaxf(sacc[j][0], sacc[j][1]));
            mx1 = fmaxf(mx1, fmaxf(sacc[j][2], sacc[j][3]));
        }
        mx0 = fmaxf(mx0, __shfl_xor_sync(0xffffffffu, mx0, 1));
        mx0 = fmaxf(mx0, __shfl_xor_sync(0xffffffffu, mx0, 2));
        mx1 = fmaxf(mx1, __shfl_xor_sync(0xffffffffu, mx1, 1));
        mx1 = fmaxf(mx1, __shfl_xor_sync(0xffffffffu, mx1, 2));
        const float mn0 = fmaxf(m0, mx0), mn1 = fmaxf(m1, mx1);
        const float cr0 = __expf(m0 - mn0), cr1 = __expf(m1 - mn1);
        m0 = mn0; m1 = mn1;
        float rs0 = 0.f, rs1 = 0.f;
        #pragma unroll
        for (int j=0;j<8;j++){
            sacc[j][0] = __expf(sacc[j][0] - mn0); rs0 += sacc[j][0];
            sacc[j][1] = __expf(sacc[j][1] - mn0); rs0 += sacc[j][1];
            sacc[j][2] = __expf(sacc[j][2] - mn1); rs1 += sacc[j][2];
            sacc[j][3] = __expf(sacc[j][3] - mn1); rs1 += sacc[j][3];
        }
        rs0 += __shfl_xor_sync(0xffffffffu, rs0, 1);
        rs0 += __shfl_xor_sync(0xffffffffu, rs0, 2);
        rs1 += __shfl_xor_sync(0xffffffffu, rs1, 1);
        rs1 += __shfl_xor_sync(0xffffffffu, rs1, 2);
        l0 = l0*cr0 + rs0;
        l1 = l1*cr1 + rs1;
        #pragma unroll
        for (int j=0;j<8;j++){
            oacc[j][0] *= cr0; oacc[j][1] *= cr0;
            oacc[j][2] *= cr1; oacc[j][3] *= cr1;
        }

        // ---- O += P V   (P packed from S accumulators in registers)
        #pragma unroll
        for (int kc=0; kc<4; kc++){
            u32 ap[4];
            ap[0] = h2pack(sacc[2*kc  ][0], sacc[2*kc  ][1]);
            ap[1] = h2pack(sacc[2*kc  ][2], sacc[2*kc  ][3]);
            ap[2] = h2pack(sacc[2*kc+1][0], sacc[2*kc+1][1]);
            ap[3] = h2pack(sacc[2*kc+1][2], sacc[2*kc+1][3]);
            #pragma unroll
            for (int nq=0; nq<4; nq++){
                u32 bfr[4];
                ldsm4(bfr, vbase + SWZ128((nq*16 + brow)*128 + (kc*16 + bkof)*2));
                mma16816h(oacc[nq*2+0], ap, bfr[0], bfr[1]);
                mma16816h(oacc[nq*2+1], ap, bfr[2], bfr[3]);
            }
        }
        slot++; if (slot >= 3) slot = 0;
    }

    // ---- epilogue: normalize, write ao [b,t,e]
    const float inv0 = 1.f / l0, inv1 = 1.f / l1;
    const int b = bh >> 5, h = bh & 31;
    const int t0 = qt*128 + wid*16 + (lane >> 2);
    float* o0 = Oo + ((size_t)(b*SEQ + t0))*EMB + h*64;
    float* o1 = o0 + 8*(size_t)EMB;
    #pragma unroll
    for (int j=0;j<8;j++){
        const int c = (j>>1)*16 + ((j&1)<<3) + ((lane&3)<<1);
        *(float2*)(o0 + c) = make_float2(oacc[j][0]*inv0, oacc[j][1]*inv0);
        *(float2*)(o1 + c) = make_float2(oacc[j][2]*inv1, oacc[j][3]*inv1);
    }
}

// =============================================================================
extern "C" void kernel_launch(void* const* d_in, const int* in_sizes, int n_in,
                              void* d_out, int out_size)
{
    (void)in_sizes; (void)n_in; (void)out_size;
    const float* x    = (const float*)d_in[0];
    const float* Wqkv = (const float*)d_in[1];
    const float* bqkv = (const float*)d_in[2];
    const float* Wout = (const float*)d_in[3];
    const float* bout = (const float*)d_in[4];
    float* out = (float*)d_out;

    float *qkv, *ao;
    __half *qh, *kh, *vt;
    __nv_bfloat16 *Ax, *Aao, *Bqkv, *Bout;
    cudaGetSymbolAddress((void**)&qkv, g_qkv);
    cudaGetSymbolAddress((void**)&ao,  g_ao);
    cudaGetSymbolAddress((void**)&qh,  g_qh);
    cudaGetSymbolAddress((void**)&kh,  g_kh);
    cudaGetSymbolAddress((void**)&vt,  g_vt);
    cudaGetSymbolAddress((void**)&Ax,   g_Ax);
    cudaGetSymbolAddress((void**)&Aao,  g_Aao);
    cudaGetSymbolAddress((void**)&Bqkv, g_Bqkv);
    cudaGetSymbolAddress((void**)&Bout, g_Bout);

    cudaFuncSetAttribute(gemm_hmma, cudaFuncAttributeMaxDynamicSharedMemorySize, GEMM_SMEM);
    cudaFuncSetAttribute(flash_hmma, cudaFuncAttributeMaxDynamicSharedMemorySize, FA_SMEM);

    // 0) split conversions
    split_rows<<<(BT*512 + 255)/256, 256>>>(x, Ax, BT);
    split_BT<<<dim3(N_QKV/32, EMB/32), dim3(32,8)>>>(Wqkv, Bqkv, N_QKV);
    split_BT<<<dim3(EMB/32,  EMB/32), dim3(32,8)>>>(Wout, Bout, EMB);

    // 1) QKV projection (tensor cores)
    gemm_hmma<<<dim3(N_QKV/256, BT/128), 512, GEMM_SMEM>>>(Ax, Bqkv, bqkv, qkv, N_QKV);

    // 2) RoPE + scatter to fp16 (V transposed)
    rope_scatter<<<BT, 256>>>(qkv, qh, kh, vt);

    // 3) causal flash attention (fp16 tensor cores)
    flash_hmma<<<dim3(SEQ/128, BATCH*NHEAD), 256, FA_SMEM>>>(qh, kh, vt, ao);

    // 4) output projection (tensor cores)
    split_rows<<<(BT*512 + 255)/256, 256>>>(ao, Aao, BT);
    gemm_hmma<<<dim3(EMB/256, BT/128), 512, GEMM_SMEM>>>(Aao, Bout, bout, out, EMB);
}

// round 10
// speedup vs baseline: 2.6794x; 1.4250x over previous
#include <cuda_runtime.h>
#include <cuda_bf16.h>
#include <cuda_fp16.h>
#include <cstdint>
#include <math.h>

typedef unsigned long long ull;
typedef unsigned int u32;

// ======================= problem constants =======================
#define BATCH   2
#define SEQ     2048
#define EMB     2048
#define NHEAD   32
#define HDIM    64
#define BT      (BATCH*SEQ)      // 4096
#define N_QKV   (3*EMB)          // 6144
#define KP      4096             // split-K' = 2*2048 (fp16 hi/lo)

// ======================= scratch (device globals) ================
__device__ float g_qkv[(size_t)BT * N_QKV];
__device__ __half g_qh[(size_t)BATCH*NHEAD*SEQ*HDIM];  // [b,h,t,d] (scaled)
__device__ __half g_kh[(size_t)BATCH*NHEAD*SEQ*HDIM];  // [b,h,t,d]
__device__ __half g_vt[(size_t)BATCH*NHEAD*HDIM*SEQ];  // [b,h,d,t] transposed
__device__ __half g_Ax  [(size_t)BT * KP];             // x split [hi, lo]
__device__ __half g_Aao [(size_t)BT * KP];             // attn-out split [hi, lo]
__device__ __half g_Bqkv[(size_t)N_QKV * KP];          // Wqkv^T [hi, hi]
__device__ __half g_Bout[(size_t)EMB * KP];            // Wout^T [hi, hi]

// ======================= helpers =================================
__device__ __forceinline__ u32 smem_u32(const void* p){
    u32 a; asm("{ .reg .u64 t; cvta.to.shared.u64 t, %1; cvt.u32.u64 %0, t; }" : "=r"(a) : "l"(p));
    return a;
}
#define SWZ128(off) ((off) ^ (((off) >> 3) & 0x70))

__device__ __forceinline__ void cpasync16(u32 daddr, const void* gptr){
    asm volatile("cp.async.cg.shared.global [%0], [%1], 16;" :: "r"(daddr), "l"(gptr));
}
#define CP_COMMIT() asm volatile("cp.async.commit_group;")
#define CP_WAIT(n)  asm volatile("cp.async.wait_group %0;" :: "n"(n))

__device__ __forceinline__ void ldsm4(u32* r, u32 addr){
    asm volatile("ldmatrix.sync.aligned.m8n8.x4.shared.b16 {%0,%1,%2,%3}, [%4];"
        : "=r"(r[0]), "=r"(r[1]), "=r"(r[2]), "=r"(r[3]) : "r"(addr));
}
__device__ __forceinline__ void mma16816h(float* c, const u32* a, u32 b0, u32 b1){
    asm volatile("mma.sync.aligned.m16n8k16.row.col.f32.f16.f16.f32 "
        "{%0,%1,%2,%3}, {%4,%5,%6,%7}, {%8,%9}, {%0,%1,%2,%3};"
        : "+f"(c[0]), "+f"(c[1]), "+f"(c[2]), "+f"(c[3])
        : "r"(a[0]), "r"(a[1]), "r"(a[2]), "r"(a[3]), "r"(b0), "r"(b1));
}
// pack two fp32 -> f16x2 register: lo half = a, hi half = b
__device__ __forceinline__ u32 h2pack(float a, float b){
    u32 r;
    asm("cvt.rn.f16x2.f32 %0, %2, %1;" : "=r"(r) : "f"(a), "f"(b));
    return r;
}

// =============================================================================
// Split conversions (fp16 hi/lo): rows [R, 2048] fp32 -> [R, 4096] fp16
// =============================================================================
__global__ void split_rows(const float* __restrict__ X, __half* __restrict__ Ap, int R)
{
    size_t idx = (size_t)blockIdx.x*blockDim.x + threadIdx.x;
    if (idx >= (size_t)R*512) return;
    int m  = (int)(idx >> 9);
    int c4 = (int)(idx & 511) * 4;
    float4 x = *(const float4*)(X + (size_t)m*2048 + c4);
    float xs[4] = {x.x, x.y, x.z, x.w};
    __half hi[4], lo[4];
    #pragma unroll
    for (int j=0;j<4;j++){
        hi[j] = __float2half_rn(xs[j]);
        lo[j] = __float2half_rn(xs[j] - __half2float(hi[j]));
    }
    __half* row = Ap + (size_t)m*KP;
    *(ull*)(row + c4)        = *(const ull*)hi;
    *(ull*)(row + 2048 + c4) = *(const ull*)lo;
}

// W [2048, N] fp32 -> Bp [N, 4096] fp16: w_hi at k AND at 2048+k
__global__ void split_BT(const float* __restrict__ W, __half* __restrict__ Bp, int N)
{
    __shared__ float tile[32][33];
    const int n0 = blockIdx.x*32, k0 = blockIdx.y*32;
    const int tx = threadIdx.x, ty = threadIdx.y;
    #pragma unroll
    for (int j=0;j<4;j++)
        tile[ty*4+j][tx] = W[(size_t)(k0+ty*4+j)*N + n0 + tx];
    __syncthreads();
    #pragma unroll
    for (int j=0;j<4;j++){
        const __half hi = __float2half_rn(tile[tx][ty*4+j]);
        __half* row = Bp + (size_t)(n0+ty*4+j)*KP + k0 + tx;
        row[0]    = hi;
        row[2048] = hi;
    }
}

// =============================================================================
// HMMA GEMM (fp16, K'=4096): C[M,N] = A'[M,KP] * B'[N,KP]^T + bias
// 128x256 CTA, 16 warps 4x4, warp 32x64, 3-stage cp.async ring, GK=64.
// =============================================================================
#define GK 64
#define NC (KP/GK)              // 64
#define STAGE_A 16384
#define STAGE_B 32768
#define STAGE   (STAGE_A + STAGE_B)
#define NSTG 3
#define GEMM_SMEM (NSTG*STAGE)

__global__ __launch_bounds__(512, 1)
void gemm_hmma(const __half* __restrict__ A,
               const __half* __restrict__ B,
               const float* __restrict__ bias,
               float* __restrict__ C, int N)
{
    extern __shared__ char smem[];
    const u32 sb = smem_u32(smem);
    const int tid  = threadIdx.x;
    const int wid  = tid >> 5;
    const int lane = tid & 31;
    const int wm = wid & 3;
    const int wn = wid >> 2;
    const int m0 = blockIdx.y * 128;
    const int n0 = blockIdx.x * 256;

    const __half* Ab = A + (size_t)m0 * KP;
    const __half* Bb = B + (size_t)n0 * KP;

    const int alr = tid >> 2;
    const int alk = (tid & 3) * 2;
    const int blr = tid >> 1;
    const int blk = (tid & 1) * 4;
    auto load_stage = [&](int kc, u32 off){
        const __half* Ag = Ab + (size_t)alr*KP + kc*GK + alk*8;
        #pragma unroll
        for (int j=0;j<2;j++)
            cpasync16(sb + off + SWZ128(alr*128 + (alk+j)*16), Ag + j*8);
        const __half* Bg = Bb + (size_t)blr*KP + kc*GK + blk*8;
        #pragma unroll
        for (int j=0;j<4;j++)
            cpasync16(sb + off + STAGE_A + SWZ128(blr*128 + (blk+j)*16), Bg + j*8);
    };

    float acc[2][8][4];
    #pragma unroll
    for (int a=0;a<2;a++)
        #pragma unroll
        for (int b=0;b<8;b++)
            #pragma unroll
            for (int c=0;c<4;c++) acc[a][b][c] = 0.f;

    load_stage(0, 0);       CP_COMMIT();
    load_stage(1, STAGE);   CP_COMMIT();

    const int arow = wm*32 + (lane & 15);
    const int akof = (lane >> 4) * 8;
    const int brow = wn*64 + ((lane >> 4) & 1)*8 + (lane & 7);
    const int bkof = ((lane >> 3) & 1) * 8;

    int slot = 0;
    for (int i=0; i<NC; i++){
        CP_WAIT(1);
        __syncthreads();

        if (i+2 < NC){
            int ns = slot + 2; if (ns >= NSTG) ns -= NSTG;
            load_stage(i+2, (u32)ns * STAGE);
        }
        CP_COMMIT();

        const u32 abase = sb + (u32)slot * STAGE;
        const u32 bbase = abase + STAGE_A;

        #pragma unroll
        for (int ks=0; ks<4; ks++){
            const int k0 = ks*16;
            u32 afr[2][4];
            #pragma unroll
            for (int mf=0; mf<2; mf++)
                ldsm4(afr[mf], abase + SWZ128((arow + mf*16)*128 + (k0 + akof)*2));
            u32 bfr[4][4];
            #pragma unroll
            for (int nq=0; nq<4; nq++)
                ldsm4(bfr[nq], bbase + SWZ128((brow + nq*16)*128 + (k0 + bkof)*2));
            #pragma unroll
            for (int mf=0; mf<2; mf++)
                #pragma unroll
                for (int nq=0; nq<4; nq++){
                    mma16816h(acc[mf][nq*2+0], afr[mf], bfr[nq][0], bfr[nq][1]);
                    mma16816h(acc[mf][nq*2+1], afr[mf], bfr[nq][2], bfr[nq][3]);
                }
        }
        slot++; if (slot >= NSTG) slot = 0;
    }

    #pragma unroll
    for (int mf=0; mf<2; mf++){
        const int r = m0 + wm*32 + mf*16 + (lane >> 2);
        #pragma unroll
        for (int nf=0; nf<8; nf++){
            const int c = n0 + wn*64 + nf*8 + (lane & 3)*2;
            const float b0 = bias[c], b1 = bias[c+1];
            float* cp = C + (size_t)r*N + c;
            *(float2*)cp = make_float2(acc[mf][nf][0] + b0, acc[mf][nf][1] + b1);
            *(float2*)(cp + 8*(size_t)N) = make_float2(acc[mf][nf][2] + b0, acc[mf][nf][3] + b1);
        }
    }
}

// =============================================================================
// RoPE + scatter to fp16: qh/kh [b,h,t,d], vt [b,h,d,t]
// =============================================================================
__global__ void rope_scatter(const float* __restrict__ qkv,
                             __half* __restrict__ qh, __half* __restrict__ kh,
                             __half* __restrict__ vt)
{
    const int bt = blockIdx.x;
    const int b = bt >> 11, t = bt & 2047;
    const float* row = qkv + (size_t)bt * N_QKV;

    for (int e = threadIdx.x; e < EMB; e += blockDim.x){
        const int h = e >> 6, d = e & 63;
        const size_t dst = ((size_t)(b*NHEAD + h) * SEQ + t) * HDIM + d;
        float qv = row[e];
        float kv = row[EMB + e];
        const float vv = row[2*EMB + e];
        if (d < 32){
            const int i = d & 15;
            const float invf = expf(-(float)i * (9.210340371976184f / 16.0f));
            const float ang = (float)t * invf;
            float sn, cs; sincosf(ang, &sn, &cs);
            if (d < 16){
                const float qx2 = row[e + 16];
                const float kx2 = row[EMB + e + 16];
                qv = qv*cs - qx2*sn;
                kv = kv*cs - kx2*sn;
            } else {
                const float qx1 = row[e - 16];
                const float kx1 = row[EMB + e - 16];
                qv = qx1*sn + qv*cs;
                kv = kx1*sn + kv*cs;
            }
        }
        qh[dst] = __float2half(qv * 0.125f);
        kh[dst] = __float2half(kv);
        vt[((size_t)(b*NHEAD + h) * HDIM + d) * SEQ + t] = __float2half(vv);
    }
}

// =============================================================================
// Flash attention, fp16 HMMA, causal. Epilogue writes hi/lo split directly
// into Aao [BT, 4096] for the out-projection GEMM.
// =============================================================================
#define FA_KV   16384
#define FA_SMEM (16384 + 3*FA_KV)        // 64 KB

__global__ __launch_bounds__(256, 2)
void flash_hmma(const __half* __restrict__ Qh, const __half* __restrict__ Kh,
                const __half* __restrict__ Vt, __half* __restrict__ Aao)
{
    extern __shared__ char smem[];
    const u32 sb = smem_u32(smem);
    const int tid = threadIdx.x, wid = tid >> 5, lane = tid & 31;
    const int qt = (int)gridDim.x - 1 - (int)blockIdx.x;   // heavy tiles first
    const int bh = blockIdx.y;
    const size_t base = (size_t)bh * SEQ * HDIM;
    const int nkt = 2*qt + 2;

    {
        const int r = tid >> 1;
        const int g = (tid & 1) * 4;
        const __half* Qg = Qh + base + (size_t)(qt*128 + r)*HDIM + g*8;
        #pragma unroll
        for (int j=0;j<4;j++)
            cpasync16(sb + SWZ128(r*128 + (g+j)*16), Qg + j*8);
    }
    const int kvr = tid >> 2;
    const int kvg = (tid & 3) * 2;
    auto load_kv = [&](int kt, u32 off){
        const __half* Kg = Kh + base + (size_t)(kt*64 + kvr)*HDIM + kvg*8;
        cpasync16(sb + off        + SWZ128(kvr*128 +  kvg   *16), Kg);
        cpasync16(sb + off        + SWZ128(kvr*128 + (kvg+1)*16), Kg + 8);
        const __half* Vg = Vt + base + (size_t)kvr*SEQ + kt*64 + kvg*8;
        cpasync16(sb + off + 8192 + SWZ128(kvr*128 +  kvg   *16), Vg);
        cpasync16(sb + off + 8192 + SWZ128(kvr*128 + (kvg+1)*16), Vg + 8);
    };

    load_kv(0, 16384);              CP_COMMIT();
    if (nkt > 1) load_kv(1, 16384 + FA_KV);
    CP_COMMIT();

    CP_WAIT(1);
    __syncthreads();

    u32 aq[4][4];
    {
        const int arow = wid*16 + (lane & 15);
        const int akof = (lane >> 4) * 8;
        #pragma unroll
        for (int ks=0; ks<4; ks++)
            ldsm4(aq[ks], sb + SWZ128(arow*128 + (ks*16 + akof)*2));
    }

    const int brow = ((lane >> 4) & 1)*8 + (lane & 7);
    const int bkof = ((lane >> 3) & 1) * 8;
    const int rq   = qt*128 + wid*16 + (lane >> 2);

    float oacc[8][4];
    #pragma unroll
    for (int j=0;j<8;j++){ oacc[j][0]=0.f; oacc[j][1]=0.f; oacc[j][2]=0.f; oacc[j][3]=0.f; }
    float m0 = -1e30f, m1 = -1e30f, l0 = 0.f, l1 = 0.f;

    int slot = 0;
    for (int kt = 0; kt < nkt; kt++){
        if (kt > 0){ CP_WAIT(1); __syncthreads(); }
        if (kt+2 < nkt){
            int ns = slot + 2; if (ns >= 3) ns -= 3;
            load_kv(kt+2, 16384 + (u32)ns*FA_KV);
        }
        CP_COMMIT();

        const u32 kbase = sb + 16384 + (u32)slot*FA_KV;
        const u32 vbase = kbase + 8192;

        float sacc[8][4];
        #pragma unroll
        for (int j=0;j<8;j++){ sacc[j][0]=0.f; sacc[j][1]=0.f; sacc[j][2]=0.f; sacc[j][3]=0.f; }
        #pragma unroll
        for (int ks=0; ks<4; ks++){
            #pragma unroll
            for (int nq=0; nq<4; nq++){
                u32 bfr[4];
                ldsm4(bfr, kbase + SWZ128((nq*16 + brow)*128 + (ks*16 + bkof)*2));
                mma16816h(sacc[nq*2+0], aq[ks], bfr[0], bfr[1]);
                mma16816h(sacc[nq*2+1], aq[ks], bfr[2], bfr[3]);
            }
        }

        if (kt >= 2*qt){
            #pragma unroll
            for (int j=0;j<8;j++){
                const int c = kt*64 + (j>>1)*16 + ((j&1)<<3) + ((lane&3)<<1);
                if (c   > rq)   sacc[j][0] = -1e30f;
                if (c+1 > rq)   sacc[j][1] = -1e30f;
                if (c   > rq+8) sacc[j][2] = -1e30f;
                if (c+1 > rq+8) sacc[j][3] = -1e30f;
            }
        }

        float mx0 = -1e30f, mx1 = -1e30f;
        #pragma unroll
        for (int j=0;j<8;j++){
            mx0 = fmaxf(mx0, fmaxf(sacc[j][0], sacc[j][1]));
            mx1 = fmaxf(mx1, fmaxf(sacc[j][2], sacc[j][3]));
        }
        mx0 = fmaxf(mx0, __shfl_xor_sync(0xffffffffu, mx0, 1));
        mx0 = fmaxf(mx0, __shfl_xor_sync(0xffffffffu, mx0, 2));
        mx1 = fmaxf(mx1, __shfl_xor_sync(0xffffffffu, mx1, 1));
        mx1 = fmaxf(mx1, __shfl_xor_sync(0xffffffffu, mx1, 2));
        const float mn0 = fmaxf(m0, mx0), mn1 = fmaxf(m1, mx1);
        const float cr0 = __expf(m0 - mn0), cr1 = __expf(m1 - mn1);
        m0 = mn0; m1 = mn1;
        float rs0 = 0.f, rs1 = 0.f;
        #pragma unroll
        for (int j=0;j<8;j++){
            sacc[j][0] = __expf(sacc[j][0] - mn0); rs0 += sacc[j][0];
            sacc[j][1] = __expf(sacc[j][1] - mn0); rs0 += sacc[j][1];
            sacc[j][2] = __expf(sacc[j][2] - mn1); rs1 += sacc[j][2];
            sacc[j][3] = __expf(sacc[j][3] - mn1); rs1 += sacc[j][3];
        }
        rs0 += __shfl_xor_sync(0xffffffffu, rs0, 1);
        rs0 += __shfl_xor_sync(0xffffffffu, rs0, 2);
        rs1 += __shfl_xor_sync(0xffffffffu, rs1, 1);
        rs1 += __shfl_xor_sync(0xffffffffu, rs1, 2);
        l0 = l0*cr0 + rs0;
        l1 = l1*cr1 + rs1;
        #pragma unroll
        for (int j=0;j<8;j++){
            oacc[j][0] *= cr0; oacc[j][1] *= cr0;
            oacc[j][2] *= cr1; oacc[j][3] *= cr1;
        }

        #pragma unroll
        for (int kc=0; kc<4; kc++){
            u32 ap[4];
            ap[0] = h2pack(sacc[2*kc  ][0], sacc[2*kc  ][1]);
            ap[1] = h2pack(sacc[2*kc  ][2], sacc[2*kc  ][3]);
            ap[2] = h2pack(sacc[2*kc+1][0], sacc[2*kc+1][1]);
            ap[3] = h2pack(sacc[2*kc+1][2], sacc[2*kc+1][3]);
            #pragma unroll
            for (int nq=0; nq<4; nq++){
                u32 bfr[4];
                ldsm4(bfr, vbase + SWZ128((nq*16 + brow)*128 + (kc*16 + bkof)*2));
                mma16816h(oacc[nq*2+0], ap, bfr[0], bfr[1]);
                mma16816h(oacc[nq*2+1], ap, bfr[2], bfr[3]);
            }
        }
        slot++; if (slot >= 3) slot = 0;
    }

    // ---- epilogue: normalize, hi/lo split, write Aao [b*SEQ+t][4096]
    const float inv0 = 1.f / l0, inv1 = 1.f / l1;
    const int b = bh >> 5, h = bh & 31;
    const int t0 = qt*128 + wid*16 + (lane >> 2);
    __half* a0 = Aao + ((size_t)(b*SEQ + t0))*KP + h*64;
    __half* a1 = a0 + 8*(size_t)KP;
    #pragma unroll
    for (int j=0;j<8;j++){
        const int c = (j>>1)*16 + ((j&1)<<3) + ((lane&3)<<1);
        float v00 = oacc[j][0]*inv0, v01 = oacc[j][1]*inv0;
        float v10 = oacc[j][2]*inv1, v11 = oacc[j][3]*inv1;
        __half h00 = __float2half_rn(v00), h01 = __float2half_rn(v01);
        __half h10 = __float2half_rn(v10), h11 = __float2half_rn(v11);
        *(u32*)(a0 + c)        = h2pack(__half2float(h00), __half2float(h01));
        *(u32*)(a0 + 2048 + c) = h2pack(v00 - __half2float(h00), v01 - __half2float(h01));
        *(u32*)(a1 + c)        = h2pack(__half2float(h10), __half2float(h11));
        *(u32*)(a1 + 2048 + c) = h2pack(v10 - __half2float(h10), v11 - __half2float(h11));
    }
}

// =============================================================================
extern "C" void kernel_launch(void* const* d_in, const int* in_sizes, int n_in,
                              void* d_out, int out_size)
{
    (void)in_sizes; (void)n_in; (void)out_size;
    const float* x    = (const float*)d_in[0];
    const float* Wqkv = (const float*)d_in[1];
    const float* bqkv = (const float*)d_in[2];
    const float* Wout = (const float*)d_in[3];
    const float* bout = (const float*)d_in[4];
    float* out = (float*)d_out;

    float *qkv;
    __half *qh, *kh, *vt, *Ax, *Aao, *Bqkv, *Bout;
    cudaGetSymbolAddress((void**)&qkv, g_qkv);
    cudaGetSymbolAddress((void**)&qh,  g_qh);
    cudaGetSymbolAddress((void**)&kh,  g_kh);
    cudaGetSymbolAddress((void**)&vt,  g_vt);
    cudaGetSymbolAddress((void**)&Ax,   g_Ax);
    cudaGetSymbolAddress((void**)&Aao,  g_Aao);
    cudaGetSymbolAddress((void**)&Bqkv, g_Bqkv);
    cudaGetSymbolAddress((void**)&Bout, g_Bout);

    cudaFuncSetAttribute(gemm_hmma, cudaFuncAttributeMaxDynamicSharedMemorySize, GEMM_SMEM);
    cudaFuncSetAttribute(flash_hmma, cudaFuncAttributeMaxDynamicSharedMemorySize, FA_SMEM);

    // 0) split conversions (fp16 hi/lo, K'=4096)
    split_rows<<<(BT*512 + 255)/256, 256>>>(x, Ax, BT);
    split_BT<<<dim3(N_QKV/32, EMB/32), dim3(32,8)>>>(Wqkv, Bqkv, N_QKV);
    split_BT<<<dim3(EMB/32,  EMB/32), dim3(32,8)>>>(Wout, Bout, EMB);

    // 1) QKV projection
    gemm_hmma<<<dim3(N_QKV/256, BT/128), 512, GEMM_SMEM>>>(Ax, Bqkv, bqkv, qkv, N_QKV);

    // 2) RoPE + scatter to fp16 (V transposed)
    rope_scatter<<<BT, 256>>>(qkv, qh, kh, vt);

    // 3) causal flash attention (fp16 tensor cores); writes Aao hi/lo directly
    flash_hmma<<<dim3(SEQ/128, BATCH*NHEAD), 256, FA_SMEM>>>(qh, kh, vt, Aao);

    // 4) output projection
    gemm_hmma<<<dim3(EMB/256, BT/128), 512, GEMM_SMEM>>>(Aao, Bout, bout, out, EMB);
}

// round 11
// speedup vs baseline: 4.2919x; 1.6018x over previous
#include <cuda_runtime.h>
#include <cuda_fp16.h>
#include <cstdint>
#include <math.h>

typedef unsigned long long ull;
typedef unsigned int u32;

// ======================= problem constants =======================
#define BATCH   2
#define SEQ     2048
#define EMB     2048
#define NHEAD   32
#define HDIM    64
#define BT      (BATCH*SEQ)      // 4096
#define N_QKV   (3*EMB)          // 6144
#define KP      2048             // plain fp16 GEMM K

// ======================= scratch (device globals) ================
__device__ float g_qkv[(size_t)BT * N_QKV];
__device__ __half g_qh[(size_t)BATCH*NHEAD*SEQ*HDIM];  // [b,h,t,d] (scaled)
__device__ __half g_kh[(size_t)BATCH*NHEAD*SEQ*HDIM];  // [b,h,t,d]
__device__ __half g_vt[(size_t)BATCH*NHEAD*HDIM*SEQ];  // [b,h,d,t] transposed
__device__ __half g_Ax  [(size_t)BT * KP];             // x fp16
__device__ __half g_Aao [(size_t)BT * KP];             // attn-out fp16
__device__ __half g_Bqkv[(size_t)N_QKV * KP];          // Wqkv^T fp16
__device__ __half g_Bout[(size_t)EMB * KP];            // Wout^T fp16

// ======================= helpers =================================
__device__ __forceinline__ u32 smem_u32(const void* p){
    u32 a; asm("{ .reg .u64 t; cvta.to.shared.u64 t, %1; cvt.u32.u64 %0, t; }" : "=r"(a) : "l"(p));
    return a;
}
#define SWZ128(off) ((off) ^ (((off) >> 3) & 0x70))

__device__ __forceinline__ void cpasync16(u32 daddr, const void* gptr){
    asm volatile("cp.async.cg.shared.global [%0], [%1], 16;" :: "r"(daddr), "l"(gptr));
}
#define CP_COMMIT() asm volatile("cp.async.commit_group;")
#define CP_WAIT(n)  asm volatile("cp.async.wait_group %0;" :: "n"(n))

__device__ __forceinline__ void ldsm4(u32* r, u32 addr){
    asm volatile("ldmatrix.sync.aligned.m8n8.x4.shared.b16 {%0,%1,%2,%3}, [%4];"
        : "=r"(r[0]), "=r"(r[1]), "=r"(r[2]), "=r"(r[3]) : "r"(addr));
}
__device__ __forceinline__ void mma16816h(float* c, const u32* a, u32 b0, u32 b1){
    asm volatile("mma.sync.aligned.m16n8k16.row.col.f32.f16.f16.f32 "
        "{%0,%1,%2,%3}, {%4,%5,%6,%7}, {%8,%9}, {%0,%1,%2,%3};"
        : "+f"(c[0]), "+f"(c[1]), "+f"(c[2]), "+f"(c[3])
        : "r"(a[0]), "r"(a[1]), "r"(a[2]), "r"(a[3]), "r"(b0), "r"(b1));
}
// pack two fp32 -> f16x2 register: lo half = a, hi half = b
__device__ __forceinline__ u32 h2pack(float a, float b){
    u32 r;
    asm("cvt.rn.f16x2.f32 %0, %2, %1;" : "=r"(r) : "f"(a), "f"(b));
    return r;
}

// =============================================================================
// Conversions
// =============================================================================
// rows [R, 2048] fp32 -> fp16
__global__ void conv_rows(const float* __restrict__ X, __half* __restrict__ Ap, int R)
{
    size_t idx = (size_t)blockIdx.x*blockDim.x + threadIdx.x;
    if (idx >= (size_t)R*512) return;
    float4 x = *(const float4*)(X + idx*4);
    __half h[4] = { __float2half_rn(x.x), __float2half_rn(x.y),
                    __float2half_rn(x.z), __float2half_rn(x.w) };
    *(ull*)(Ap + idx*4) = *(const ull*)h;
}

// W [2048, N] fp32 -> Bp [N, 2048] fp16 (transpose)
__global__ void conv_BT(const float* __restrict__ W, __half* __restrict__ Bp, int N)
{
    __shared__ float tile[32][33];
    const int n0 = blockIdx.x*32, k0 = blockIdx.y*32;
    const int tx = threadIdx.x, ty = threadIdx.y;
    #pragma unroll
    for (int j=0;j<4;j++)
        tile[ty*4+j][tx] = W[(size_t)(k0+ty*4+j)*N + n0 + tx];
    __syncthreads();
    #pragma unroll
    for (int j=0;j<4;j++)
        Bp[(size_t)(n0+ty*4+j)*KP + k0 + tx] = __float2half_rn(tile[tx][ty*4+j]);
}

// =============================================================================
// HMMA GEMM (fp16, K=2048): C[M,N] = A[M,KP] * B[N,KP]^T + bias
// 128x256 CTA, 16 warps 4x4, warp 32x64, 3-stage cp.async ring, GK=64.
// =============================================================================
#define GK 64
#define NC (KP/GK)              // 32
#define STAGE_A 16384
#define STAGE_B 32768
#define STAGE   (STAGE_A + STAGE_B)
#define NSTG 3
#define GEMM_SMEM (NSTG*STAGE)

__global__ __launch_bounds__(512, 1)
void gemm_hmma(const __half* __restrict__ A,
               const __half* __restrict__ B,
               const float* __restrict__ bias,
               float* __restrict__ C, int N)
{
    extern __shared__ char smem[];
    const u32 sb = smem_u32(smem);
    const int tid  = threadIdx.x;
    const int wid  = tid >> 5;
    const int lane = tid & 31;
    const int wm = wid & 3;
    const int wn = wid >> 2;
    const int m0 = blockIdx.y * 128;
    const int n0 = blockIdx.x * 256;

    const __half* Ab = A + (size_t)m0 * KP;
    const __half* Bb = B + (size_t)n0 * KP;

    const int alr = tid >> 2;
    const int alk = (tid & 3) * 2;
    const int blr = tid >> 1;
    const int blk = (tid & 1) * 4;
    auto load_stage = [&](int kc, u32 off){
        const __half* Ag = Ab + (size_t)alr*KP + kc*GK + alk*8;
        #pragma unroll
        for (int j=0;j<2;j++)
            cpasync16(sb + off + SWZ128(alr*128 + (alk+j)*16), Ag + j*8);
        const __half* Bg = Bb + (size_t)blr*KP + kc*GK + blk*8;
        #pragma unroll
        for (int j=0;j<4;j++)
            cpasync16(sb + off + STAGE_A + SWZ128(blr*128 + (blk+j)*16), Bg + j*8);
    };

    float acc[2][8][4];
    #pragma unroll
    for (int a=0;a<2;a++)
        #pragma unroll
        for (int b=0;b<8;b++)
            #pragma unroll
            for (int c=0;c<4;c++) acc[a][b][c] = 0.f;

    load_stage(0, 0);       CP_COMMIT();
    load_stage(1, STAGE);   CP_COMMIT();

    const int arow = wm*32 + (lane & 15);
    const int akof = (lane >> 4) * 8;
    const int brow = wn*64 + ((lane >> 4) & 1)*8 + (lane & 7);
    const int bkof = ((lane >> 3) & 1) * 8;

    int slot = 0;
    for (int i=0; i<NC; i++){
        CP_WAIT(1);
        __syncthreads();

        if (i+2 < NC){
            int ns = slot + 2; if (ns >= NSTG) ns -= NSTG;
            load_stage(i+2, (u32)ns * STAGE);
        }
        CP_COMMIT();

        const u32 abase = sb + (u32)slot * STAGE;
        const u32 bbase = abase + STAGE_A;

        #pragma unroll
        for (int ks=0; ks<4; ks++){
            const int k0 = ks*16;
            u32 afr[2][4];
            #pragma unroll
            for (int mf=0; mf<2; mf++)
                ldsm4(afr[mf], abase + SWZ128((arow + mf*16)*128 + (k0 + akof)*2));
            u32 bfr[4][4];
            #pragma unroll
            for (int nq=0; nq<4; nq++)
                ldsm4(bfr[nq], bbase + SWZ128((brow + nq*16)*128 + (k0 + bkof)*2));
            #pragma unroll
            for (int mf=0; mf<2; mf++)
                #pragma unroll
                for (int nq=0; nq<4; nq++){
                    mma16816h(acc[mf][nq*2+0], afr[mf], bfr[nq][0], bfr[nq][1]);
                    mma16816h(acc[mf][nq*2+1], afr[mf], bfr[nq][2], bfr[nq][3]);
                }
        }
        slot++; if (slot >= NSTG) slot = 0;
    }

    #pragma unroll
    for (int mf=0; mf<2; mf++){
        const int r = m0 + wm*32 + mf*16 + (lane >> 2);
        #pragma unroll
        for (int nf=0; nf<8; nf++){
            const int c = n0 + wn*64 + nf*8 + (lane & 3)*2;
            const float b0 = bias[c], b1 = bias[c+1];
            float* cp = C + (size_t)r*N + c;
            *(float2*)cp = make_float2(acc[mf][nf][0] + b0, acc[mf][nf][1] + b1);
            *(float2*)(cp + 8*(size_t)N) = make_float2(acc[mf][nf][2] + b0, acc[mf][nf][3] + b1);
        }
    }
}

// =============================================================================
// RoPE + scatter to fp16: qh/kh [b,h,t,d], vt [b,h,d,t]
// =============================================================================
__global__ void rope_scatter(const float* __restrict__ qkv,
                             __half* __restrict__ qh, __half* __restrict__ kh,
                             __half* __restrict__ vt)
{
    const int bt = blockIdx.x;
    const int b = bt >> 11, t = bt & 2047;
    const float* row = qkv + (size_t)bt * N_QKV;

    for (int e = threadIdx.x; e < EMB; e += blockDim.x){
        const int h = e >> 6, d = e & 63;
        const size_t dst = ((size_t)(b*NHEAD + h) * SEQ + t) * HDIM + d;
        float qv = row[e];
        float kv = row[EMB + e];
        const float vv = row[2*EMB + e];
        if (d < 32){
            const int i = d & 15;
            const float invf = expf(-(float)i * (9.210340371976184f / 16.0f));
            const float ang = (float)t * invf;
            float sn, cs; sincosf(ang, &sn, &cs);
            if (d < 16){
                const float qx2 = row[e + 16];
                const float kx2 = row[EMB + e + 16];
                qv = qv*cs - qx2*sn;
                kv = kv*cs - kx2*sn;
            } else {
                const float qx1 = row[e - 16];
                const float kx1 = row[EMB + e - 16];
                qv = qx1*sn + qv*cs;
                kv = kx1*sn + kv*cs;
            }
        }
        qh[dst] = __float2half(qv * 0.125f);
        kh[dst] = __float2half(kv);
        vt[((size_t)(b*NHEAD + h) * HDIM + d) * SEQ + t] = __float2half(vv);
    }
}

// =============================================================================
// Flash attention, fp16 HMMA, causal. Epilogue writes fp16 Aao [BT, 2048].
// =============================================================================
#define FA_KV   16384
#define FA_SMEM (16384 + 3*FA_KV)        // 64 KB

__global__ __launch_bounds__(256, 2)
void flash_hmma(const __half* __restrict__ Qh, const __half* __restrict__ Kh,
                const __half* __restrict__ Vt, __half* __restrict__ Aao)
{
    extern __shared__ char smem[];
    const u32 sb = smem_u32(smem);
    const int tid = threadIdx.x, wid = tid >> 5, lane = tid & 31;
    const int qt = (int)gridDim.x - 1 - (int)blockIdx.x;   // heavy tiles first
    const int bh = blockIdx.y;
    const size_t base = (size_t)bh * SEQ * HDIM;
    const int nkt = 2*qt + 2;

    {
        const int r = tid >> 1;
        const int g = (tid & 1) * 4;
        const __half* Qg = Qh + base + (size_t)(qt*128 + r)*HDIM + g*8;
        #pragma unroll
        for (int j=0;j<4;j++)
            cpasync16(sb + SWZ128(r*128 + (g+j)*16), Qg + j*8);
    }
    const int kvr = tid >> 2;
    const int kvg = (tid & 3) * 2;
    auto load_kv = [&](int kt, u32 off){
        const __half* Kg = Kh + base + (size_t)(kt*64 + kvr)*HDIM + kvg*8;
        cpasync16(sb + off        + SWZ128(kvr*128 +  kvg   *16), Kg);
        cpasync16(sb + off        + SWZ128(kvr*128 + (kvg+1)*16), Kg + 8);
        const __half* Vg = Vt + base + (size_t)kvr*SEQ + kt*64 + kvg*8;
        cpasync16(sb + off + 8192 + SWZ128(kvr*128 +  kvg   *16), Vg);
        cpasync16(sb + off + 8192 + SWZ128(kvr*128 + (kvg+1)*16), Vg + 8);
    };

    load_kv(0, 16384);              CP_COMMIT();
    if (nkt > 1) load_kv(1, 16384 + FA_KV);
    CP_COMMIT();

    CP_WAIT(1);
    __syncthreads();

    u32 aq[4][4];
    {
        const int arow = wid*16 + (lane & 15);
        const int akof = (lane >> 4) * 8;
        #pragma unroll
        for (int ks=0; ks<4; ks++)
            ldsm4(aq[ks], sb + SWZ128(arow*128 + (ks*16 + akof)*2));
    }

    const int brow = ((lane >> 4) & 1)*8 + (lane & 7);
    const int bkof = ((lane >> 3) & 1) * 8;
    const int rq   = qt*128 + wid*16 + (lane >> 2);

    float oacc[8][4];
    #pragma unroll
    for (int j=0;j<8;j++){ oacc[j][0]=0.f; oacc[j][1]=0.f; oacc[j][2]=0.f; oacc[j][3]=0.f; }
    float m0 = -1e30f, m1 = -1e30f, l0 = 0.f, l1 = 0.f;

    int slot = 0;
    for (int kt = 0; kt < nkt; kt++){
        if (kt > 0){ CP_WAIT(1); __syncthreads(); }
        if (kt+2 < nkt){
            int ns = slot + 2; if (ns >= 3) ns -= 3;
            load_kv(kt+2, 16384 + (u32)ns*FA_KV);
        }
        CP_COMMIT();

        const u32 kbase = sb + 16384 + (u32)slot*FA_KV;
        const u32 vbase = kbase + 8192;

        float sacc[8][4];
        #pragma unroll
        for (int j=0;j<8;j++){ sacc[j][0]=0.f; sacc[j][1]=0.f; sacc[j][2]=0.f; sacc[j][3]=0.f; }
        #pragma unroll
        for (int ks=0; ks<4; ks++){
            #pragma unroll
            for (int nq=0; nq<4; nq++){
                u32 bfr[4];
                ldsm4(bfr, kbase + SWZ128((nq*16 + brow)*128 + (ks*16 + bkof)*2));
                mma16816h(sacc[nq*2+0], aq[ks], bfr[0], bfr[1]);
                mma16816h(sacc[nq*2+1], aq[ks], bfr[2], bfr[3]);
            }
        }

        if (kt >= 2*qt){
            #pragma unroll
            for (int j=0;j<8;j++){
                const int c = kt*64 + (j>>1)*16 + ((j&1)<<3) + ((lane&3)<<1);
                if (c   > rq)   sacc[j][0] = -1e30f;
                if (c+1 > rq)   sacc[j][1] = -1e30f;
                if (c   > rq+8) sacc[j][2] = -1e30f;
                if (c+1 > rq+8) sacc[j][3] = -1e30f;
            }
        }

        float mx0 = -1e30f, mx1 = -1e30f;
        #pragma unroll
        for (int j=0;j<8;j++){
            mx0 = fmaxf(mx0, fmaxf(sacc[j][0], sacc[j][1]));
            mx1 = fmaxf(mx1, fmaxf(sacc[j][2], sacc[j][3]));
        }
        mx0 = fmaxf(mx0, __shfl_xor_sync(0xffffffffu, mx0, 1));
        mx0 = fmaxf(mx0, __shfl_xor_sync(0xffffffffu, mx0, 2));
        mx1 = fmaxf(mx1, __shfl_xor_sync(0xffffffffu, mx1, 1));
        mx1 = fmaxf(mx1, __shfl_xor_sync(0xffffffffu, mx1, 2));
        const float mn0 = fmaxf(m0, mx0), mn1 = fmaxf(m1, mx1);
        const float cr0 = __expf(m0 - mn0), cr1 = __expf(m1 - mn1);
        m0 = mn0; m1 = mn1;
        float rs0 = 0.f, rs1 = 0.f;
        #pragma unroll
        for (int j=0;j<8;j++){
            sacc[j][0] = __expf(sacc[j][0] - mn0); rs0 += sacc[j][0];
            sacc[j][1] = __expf(sacc[j][1] - mn0); rs0 += sacc[j][1];
            sacc[j][2] = __expf(sacc[j][2] - mn1); rs1 += sacc[j][2];
            sacc[j][3] = __expf(sacc[j][3] - mn1); rs1 += sacc[j][3];
        }
        rs0 += __shfl_xor_sync(0xffffffffu, rs0, 1);
        rs0 += __shfl_xor_sync(0xffffffffu, rs0, 2);
        rs1 += __shfl_xor_sync(0xffffffffu, rs1, 1);
        rs1 += __shfl_xor_sync(0xffffffffu, rs1, 2);
        l0 = l0*cr0 + rs0;
        l1 = l1*cr1 + rs1;
        #pragma unroll
        for (int j=0;j<8;j++){
            oacc[j][0] *= cr0; oacc[j][1] *= cr0;
            oacc[j][2] *= cr1; oacc[j][3] *= cr1;
        }

        #pragma unroll
        for (int kc=0; kc<4; kc++){
            u32 ap[4];
            ap[0] = h2pack(sacc[2*kc  ][0], sacc[2*kc  ][1]);
            ap[1] = h2pack(sacc[2*kc  ][2], sacc[2*kc  ][3]);
            ap[2] = h2pack(sacc[2*kc+1][0], sacc[2*kc+1][1]);
            ap[3] = h2pack(sacc[2*kc+1][2], sacc[2*kc+1][3]);
            #pragma unroll
            for (int nq=0; nq<4; nq++){
                u32 bfr[4];
                ldsm4(bfr, vbase + SWZ128((nq*16 + brow)*128 + (kc*16 + bkof)*2));
                mma16816h(oacc[nq*2+0], ap, bfr[0], bfr[1]);
                mma16816h(oacc[nq*2+1], ap, bfr[2], bfr[3]);
            }
        }
        slot++; if (slot >= 3) slot = 0;
    }

    // ---- epilogue: normalize, write fp16 Aao [b*SEQ+t][2048]
    const float inv0 = 1.f / l0, inv1 = 1.f / l1;
    const int b = bh >> 5, h = bh & 31;
    const int t0 = qt*128 + wid*16 + (lane >> 2);
    __half* a0 = Aao + ((size_t)(b*SEQ + t0))*EMB + h*64;
    __half* a1 = a0 + 8*(size_t)EMB;
    #pragma unroll
    for (int j=0;j<8;j++){
        const int c = (j>>1)*16 + ((j&1)<<3) + ((lane&3)<<1);
        *(u32*)(a0 + c) = h2pack(oacc[j][0]*inv0, oacc[j][1]*inv0);
        *(u32*)(a1 + c) = h2pack(oacc[j][2]*inv1, oacc[j][3]*inv1);
    }
}

// =============================================================================
extern "C" void kernel_launch(void* const* d_in, const int* in_sizes, int n_in,
                              void* d_out, int out_size)
{
    (void)in_sizes; (void)n_in; (void)out_size;
    const float* x    = (const float*)d_in[0];
    const float* Wqkv = (const float*)d_in[1];
    const float* bqkv = (const float*)d_in[2];
    const float* Wout = (const float*)d_in[3];
    const float* bout = (const float*)d_in[4];
    float* out = (float*)d_out;

    float *qkv;
    __half *qh, *kh, *vt, *Ax, *Aao, *Bqkv, *Bout;
    cudaGetSymbolAddress((void**)&qkv, g_qkv);
    cudaGetSymbolAddress((void**)&qh,  g_qh);
    cudaGetSymbolAddress((void**)&kh,  g_kh);
    cudaGetSymbolAddress((void**)&vt,  g_vt);
    cudaGetSymbolAddress((void**)&Ax,   g_Ax);
    cudaGetSymbolAddress((void**)&Aao,  g_Aao);
    cudaGetSymbolAddress((void**)&Bqkv, g_Bqkv);
    cudaGetSymbolAddress((void**)&Bout, g_Bout);

    cudaFuncSetAttribute(gemm_hmma, cudaFuncAttributeMaxDynamicSharedMemorySize, GEMM_SMEM);
    cudaFuncSetAttribute(flash_hmma, cudaFuncAttributeMaxDynamicSharedMemorySize, FA_SMEM);

    // 0) fp16 conversions
    conv_rows<<<(BT*512 + 255)/256, 256>>>(x, Ax, BT);
    conv_BT<<<dim3(N_QKV/32, EMB/32), dim3(32,8)>>>(Wqkv, Bqkv, N_QKV);
    conv_BT<<<dim3(EMB/32,  EMB/32), dim3(32,8)>>>(Wout, Bout, EMB);

    // 1) QKV projection (fp16 HMMA, K=2048)
    gemm_hmma<<<dim3(N_QKV/256, BT/128), 512, GEMM_SMEM>>>(Ax, Bqkv, bqkv, qkv, N_QKV);

    // 2) RoPE + scatter to fp16 (V transposed)
    rope_scatter<<<BT, 256>>>(qkv, qh, kh, vt);

    // 3) causal flash attention (fp16 tensor cores); writes fp16 Aao
    flash_hmma<<<dim3(SEQ/128, BATCH*NHEAD), 256, FA_SMEM>>>(qh, kh, vt, Aao);

    // 4) output projection (fp16 HMMA, K=2048)
    gemm_hmma<<<dim3(EMB/256, BT/128), 512, GEMM_SMEM>>>(Aao, Bout, bout, out, EMB);
}